// round 10
// baseline (speedup 1.0000x reference)
#include <cuda_runtime.h>
#include <cuda_fp16.h>
#include <math.h>

#define B_   64
#define N_   197
#define C_   768
#define H_   12
#define R_   98
#define K_   99
#define NKEPT_ 98
#define THRK_ 1941
#define ALPHA_ 0.1f
#define EPS_ 1e-5f
#define BH_  (B_*H_)

// ---------------- scratch ----------------
__device__ float    g_qkv [(size_t)B_*N_*3*C_];
__device__ float    g_attn[(size_t)BH_*N_*N_];
__device__ __half   g_attnh[(size_t)BH_*256*224];   // padded fp16 softmax probs
__device__ float    g_x1  [(size_t)B_*N_*C_];
__device__ float    g_x2  [(size_t)B_*K_*C_];
__device__ int      g_ik  [B_*K_];
__device__ int      g_ie  [B_*R_];
__device__ unsigned g_hh  [(size_t)B_*N_*C_/2];
__device__ unsigned g_hl  [(size_t)B_*N_*C_/2];
__device__ __half   g_wqkvh[(size_t)C_*3*C_];
__device__ __half   g_wqkvl[(size_t)C_*3*C_];
__device__ __half   g_wprojh[(size_t)C_*C_];
__device__ __half   g_wfc1h[(size_t)C_*4*C_];
__device__ __half   g_wfc2h[(size_t)4*C_*C_];
__device__ unsigned g_aoh [(size_t)B_*N_*C_/2];
__device__ unsigned g_h2h [(size_t)B_*K_*C_/2];
__device__ unsigned g_mlph[(size_t)B_*K_*4*C_/2];

// ---------------- helpers ----------------
__device__ __forceinline__ unsigned packh2(float a, float b) {
    __half2 h = __floats2half2_rn(a, b);
    return *reinterpret_cast<unsigned*>(&h);
}
__device__ __forceinline__ void splith2(float a, float b, unsigned& hi, unsigned& lo) {
    __half ah = __float2half_rn(a), bh = __float2half_rn(b);
    __half2 h = __halves2half2(ah, bh);
    hi = *reinterpret_cast<unsigned*>(&h);
    lo = packh2(a - __half2float(ah), b - __half2float(bh));
}
__device__ __forceinline__ unsigned sm_u32(const void* p) {
    return (unsigned)__cvta_generic_to_shared(p);
}
__device__ __forceinline__ void ldsm4(unsigned r[4], unsigned a) {
    asm volatile("ldmatrix.sync.aligned.m8n8.x4.shared.b16 {%0,%1,%2,%3}, [%4];"
                 : "=r"(r[0]), "=r"(r[1]), "=r"(r[2]), "=r"(r[3]) : "r"(a));
}
__device__ __forceinline__ void ldsm4t(unsigned r[4], unsigned a) {
    asm volatile("ldmatrix.sync.aligned.m8n8.x4.trans.shared.b16 {%0,%1,%2,%3}, [%4];"
                 : "=r"(r[0]), "=r"(r[1]), "=r"(r[2]), "=r"(r[3]) : "r"(a));
}
__device__ __forceinline__ void mma_f16(float c[4], const unsigned a[4], const unsigned b[2]) {
    asm volatile(
        "mma.sync.aligned.m16n8k16.row.col.f32.f16.f16.f32 "
        "{%0,%1,%2,%3},{%4,%5,%6,%7},{%8,%9},{%0,%1,%2,%3};"
        : "+f"(c[0]), "+f"(c[1]), "+f"(c[2]), "+f"(c[3])
        : "r"(a[0]), "r"(a[1]), "r"(a[2]), "r"(a[3]), "r"(b[0]), "r"(b[1]));
}

// ---------------- weight convert: fp32 [K][N] -> half [K][N] (hi, opt lo) ----------
template<int SPLIT>
__global__ void cvtw_h(const float* __restrict__ w, __half* __restrict__ hi,
                       __half* __restrict__ lo, int n)
{
    int i = (blockIdx.x * 256 + threadIdx.x) * 8;
    if (i >= n) return;
    float4 a = *(const float4*)&w[i];
    float4 b = *(const float4*)&w[i + 4];
    __half2 h[4];
    h[0] = __floats2half2_rn(a.x, a.y); h[1] = __floats2half2_rn(a.z, a.w);
    h[2] = __floats2half2_rn(b.x, b.y); h[3] = __floats2half2_rn(b.z, b.w);
    *(uint4*)&hi[i] = *(uint4*)h;
    if (SPLIT) {
        __half2 l[4];
        l[0] = __floats2half2_rn(a.x - __low2float(h[0]), a.y - __high2float(h[0]));
        l[1] = __floats2half2_rn(a.z - __low2float(h[1]), a.w - __high2float(h[1]));
        l[2] = __floats2half2_rn(b.x - __low2float(h[2]), b.y - __high2float(h[2]));
        l[3] = __floats2half2_rn(b.z - __low2float(h[3]), b.w - __high2float(h[3]));
        *(uint4*)&lo[i] = *(uint4*)l;
    }
}

// ---------------- LayerNorm -> packed fp16 hi(/lo) ----------------
template<int SPLIT>
__global__ void ln_pack_kernel(const float* __restrict__ x, const float* __restrict__ g,
                               const float* __restrict__ bta,
                               unsigned* __restrict__ hi, unsigned* __restrict__ lo)
{
    int row = blockIdx.x;
    const float2* xr = (const float2*)(x + (size_t)row * C_);
    int tid = threadIdx.x;
    float2 v1 = xr[tid];
    float2 v2 = make_float2(0.f, 0.f);
    if (tid < 128) v2 = xr[tid + 256];
    float s = v1.x + v1.y + v2.x + v2.y;
    float ss = v1.x * v1.x + v1.y * v1.y + v2.x * v2.x + v2.y * v2.y;
    for (int off = 16; off; off >>= 1) {
        s  += __shfl_xor_sync(0xffffffffu, s, off);
        ss += __shfl_xor_sync(0xffffffffu, ss, off);
    }
    __shared__ float rs[8], rss[8];
    __shared__ float smean, srstd;
    int w = tid >> 5;
    if ((tid & 31) == 0) { rs[w] = s; rss[w] = ss; }
    __syncthreads();
    if (tid == 0) {
        float S = 0.f, SS = 0.f;
        for (int i = 0; i < 8; i++) { S += rs[i]; SS += rss[i]; }
        float mean = S * (1.f / C_);
        float var = SS * (1.f / C_) - mean * mean;
        smean = mean; srstd = rsqrtf(var + EPS_);
    }
    __syncthreads();
    float mean = smean, rstd = srstd;
    size_t base = (size_t)row * (C_ / 2);
#pragma unroll
    for (int p = 0; p < 2; p++) {
        if (p == 1 && tid >= 128) break;
        int wi = tid + p * 256;
        float2 v = (p == 0) ? v1 : v2;
        int c = wi * 2;
        float a = (v.x - mean) * rstd * g[c] + bta[c];
        float b = (v.y - mean) * rstd * g[c + 1] + bta[c + 1];
        if (SPLIT) { unsigned h, l; splith2(a, b, h, l); hi[base + wi] = h; lo[base + wi] = l; }
        else hi[base + wi] = packh2(a, b);
    }
}

// ---------------- fp16 GEMM: 64x256 tile, k32 steps, ldmatrix, double-buffered ----
#define AST 40
#define BST 264
#define ABUF (64 * AST)
#define BBUF (32 * BST)

template<int SPLIT>
__device__ __forceinline__ void hg_compute(const __half* buf, const int aoff[2],
                                           const int boff[4], float acc[2][8][4])
{
    const __half* AsH = buf;
    const __half* AsL = buf + ABUF;
    const __half* BsH = buf + ABUF * (1 + SPLIT);
    const __half* BsL = BsH + BBUF;
#pragma unroll
    for (int s = 0; s < 2; s++) {
        unsigned ah[2][4], al[2][4];
#pragma unroll
        for (int mf = 0; mf < 2; mf++) {
            ldsm4(ah[mf], sm_u32(AsH + aoff[mf] + s * 16));
            if (SPLIT) ldsm4(al[mf], sm_u32(AsL + aoff[mf] + s * 16));
        }
        unsigned bhf[8][2], blf[8][2];
#pragma unroll
        for (int p = 0; p < 4; p++) {
            unsigned r[4];
            ldsm4t(r, sm_u32(BsH + boff[p] + s * 16 * BST));
            bhf[2*p][0] = r[0]; bhf[2*p][1] = r[1];
            bhf[2*p+1][0] = r[2]; bhf[2*p+1][1] = r[3];
            if (SPLIT) {
                unsigned rl[4];
                ldsm4t(rl, sm_u32(BsL + boff[p] + s * 16 * BST));
                blf[2*p][0] = rl[0]; blf[2*p][1] = rl[1];
                blf[2*p+1][0] = rl[2]; blf[2*p+1][1] = rl[3];
            }
        }
#pragma unroll
        for (int mf = 0; mf < 2; mf++)
#pragma unroll
            for (int nf = 0; nf < 8; nf++) {
                mma_f16(acc[mf][nf], ah[mf], bhf[nf]);
                if (SPLIT) {
                    mma_f16(acc[mf][nf], ah[mf], blf[nf]);
                    mma_f16(acc[mf][nf], al[mf], bhf[nf]);
                }
            }
    }
}

template<int SPLIT, bool GELU, bool HASBIAS, bool HASRES, bool OUTPACK>
__global__ void __launch_bounds__(256, 2)
hgemm_kernel(const unsigned* __restrict__ Ah, const unsigned* __restrict__ Al,
             const __half* __restrict__ Bh, const __half* __restrict__ Bl,
             const float* __restrict__ bias, const float* __restrict__ res,
             float* __restrict__ Cf, unsigned* __restrict__ Cu,
             int Nd, int Kd, int ldc, int n0ofs)
{
    extern __shared__ __half sh[];
    const int UNIT = (ABUF + BBUF) * (1 + SPLIT);
    int tid = threadIdx.x, lane = tid & 31, wid = tid >> 5;
    int wm = wid & 1, wn = wid >> 1;
    int g = lane >> 2, tg = lane & 3;
    int m0 = blockIdx.y * 64, n0 = blockIdx.x * 256 + n0ofs;
    int Kw = Kd / 2;

    float acc[2][8][4];
#pragma unroll
    for (int i = 0; i < 2; i++)
#pragma unroll
        for (int j = 0; j < 8; j++)
#pragma unroll
            for (int q = 0; q < 4; q++) acc[i][j][q] = 0.f;

    int ar = tid >> 2, agw = (tid & 3) * 4;
    int bkr = tid >> 5, bn8 = (tid & 31) * 8;
    const unsigned* ApH = Ah + (size_t)(m0 + ar) * Kw + agw;
    const unsigned* ApL = SPLIT ? Al + (size_t)(m0 + ar) * Kw + agw : ApH;
    const __half* BpH = Bh + (size_t)bkr * Nd + n0 + bn8;
    const __half* BpL = SPLIT ? Bl + (size_t)bkr * Nd + n0 + bn8 : BpH;

    int aSts = ar * AST + (tid & 3) * 8;
    int bSts = bkr * BST + bn8;

    int aoff[2], boff[4];
#pragma unroll
    for (int mf = 0; mf < 2; mf++)
        aoff[mf] = (wm * 32 + mf * 16 + (lane & 15)) * AST + (lane >> 4) * 8;
#pragma unroll
    for (int p = 0; p < 4; p++)
        boff[p] = (lane & 15) * BST + wn * 64 + p * 16 + (lane >> 4) * 8;

    uint4 rah, ral, rbh[4], rbl[4];
    rah = *(const uint4*)ApH;
    if (SPLIT) ral = *(const uint4*)ApL;
#pragma unroll
    for (int j = 0; j < 4; j++) {
        rbh[j] = *(const uint4*)(BpH + (size_t)j * 8 * Nd);
        if (SPLIT) rbl[j] = *(const uint4*)(BpL + (size_t)j * 8 * Nd);
    }
    {
        __half* buf = sh;
        *(uint4*)&buf[aSts] = rah;
        if (SPLIT) *(uint4*)&buf[ABUF + aSts] = ral;
        __half* bb = buf + ABUF * (1 + SPLIT);
#pragma unroll
        for (int j = 0; j < 4; j++) {
            *(uint4*)&bb[bSts + j * 8 * BST] = rbh[j];
            if (SPLIT) *(uint4*)&bb[BBUF + bSts + j * 8 * BST] = rbl[j];
        }
    }
    __syncthreads();

    int nit = Kd / 32;
    for (int it = 1; it < nit; it++) {
        rah = *(const uint4*)(ApH + it * 16);
        if (SPLIT) ral = *(const uint4*)(ApL + it * 16);
#pragma unroll
        for (int j = 0; j < 4; j++) {
            rbh[j] = *(const uint4*)(BpH + (size_t)(it * 32 + j * 8) * Nd);
            if (SPLIT) rbl[j] = *(const uint4*)(BpL + (size_t)(it * 32 + j * 8) * Nd);
        }
        hg_compute<SPLIT>(sh + ((it - 1) & 1) * UNIT, aoff, boff, acc);
        {
            __half* buf = sh + (it & 1) * UNIT;
            *(uint4*)&buf[aSts] = rah;
            if (SPLIT) *(uint4*)&buf[ABUF + aSts] = ral;
            __half* bb = buf + ABUF * (1 + SPLIT);
#pragma unroll
            for (int j = 0; j < 4; j++) {
                *(uint4*)&bb[bSts + j * 8 * BST] = rbh[j];
                if (SPLIT) *(uint4*)&bb[BBUF + bSts + j * 8 * BST] = rbl[j];
            }
        }
        __syncthreads();
    }
    hg_compute<SPLIT>(sh + ((nit - 1) & 1) * UNIT, aoff, boff, acc);

    // epilogue
#pragma unroll
    for (int mf = 0; mf < 2; mf++) {
        int row = m0 + wm * 32 + mf * 16 + g;
#pragma unroll
        for (int nf = 0; nf < 8; nf++) {
            int col = n0 + wn * 64 + nf * 8 + 2 * tg;
            float b0 = 0.f, b1 = 0.f;
            if (HASBIAS) { b0 = bias[col]; b1 = bias[col + 1]; }
#pragma unroll
            for (int half = 0; half < 2; half++) {
                int r = row + half * 8;
                float c0 = acc[mf][nf][half * 2 + 0] + b0;
                float c1 = acc[mf][nf][half * 2 + 1] + b1;
                if (GELU) {
                    c0 = 0.5f * c0 * (1.f + erff(c0 * 0.70710678118654752f));
                    c1 = 0.5f * c1 * (1.f + erff(c1 * 0.70710678118654752f));
                }
                if (OUTPACK) {
                    Cu[(size_t)r * (Nd / 2) + col / 2] = packh2(c0, c1);
                } else {
                    size_t base = (size_t)r * ldc + col;
                    if (HASRES) {
                        float2 rv = *(const float2*)&res[base];
                        c0 += rv.x; c1 += rv.y;
                    }
                    float2 ov; ov.x = c0; ov.y = c1;
                    *(float2*)&Cf[base] = ov;
                }
            }
        }
    }
}

// ---------------- fused scores + softmax: split-fp16 MMA, 64 rows x full 224 cols ----
__global__ void fsm_kernel(const float* __restrict__ qkv, float* __restrict__ attn,
                           __half* __restrict__ attnh)
{
    __shared__ unsigned Qh[64 * 36], Ql[64 * 36], Kh[32 * 72], Kl[32 * 72];
    __shared__ float red[2][2][64];
    int bh = blockIdx.x, b = bh / H_, hh = bh % H_;
    int m0 = blockIdx.y * 64;
    int tid = threadIdx.x, lane = tid & 31, wid = tid >> 5;
    int g = lane >> 2, tg = lane & 3;
    int wm = wid & 3, wn = wid >> 2;

    // Q tile (64 rows x 32 words), split-fp16
#pragma unroll
    for (int r = 0; r < 8; r++) {
        int idx = tid + r * 256;
        int row = idx >> 5, kw = idx & 31;
        int mq = m0 + row;
        float2 qv = make_float2(0.f, 0.f);
        if (mq < N_) qv = *(const float2*)&qkv[(size_t)(b * N_ + mq) * 2304 + hh * 64 + 2 * kw];
        unsigned h, l;
        splith2(qv.x * 0.125f, qv.y * 0.125f, h, l);
        Qh[row * 36 + kw] = h; Ql[row * 36 + kw] = l;
    }

    float acc[4][4][4];
#pragma unroll
    for (int c = 0; c < 4; c++)
#pragma unroll
        for (int j = 0; j < 4; j++)
#pragma unroll
            for (int q = 0; q < 4; q++) acc[c][j][q] = 0.f;

    for (int c = 0; c < 4; c++) {
        int n0 = c * 64;
        __syncthreads();
#pragma unroll
        for (int r = 0; r < 8; r++) {
            int idx = tid + r * 256;
            int row = idx >> 5, kw = idx & 31;
            int nk = n0 + row;
            float2 kv = make_float2(0.f, 0.f);
            if (nk < N_) kv = *(const float2*)&qkv[(size_t)(b * N_ + nk) * 2304 + 768 + hh * 64 + 2 * kw];
            unsigned h, l;
            splith2(kv.x, kv.y, h, l);
            Kh[kw * 72 + row] = h; Kl[kw * 72 + row] = l;
        }
        __syncthreads();
#pragma unroll
        for (int s = 0; s < 4; s++) {
            int abase = (wm * 16 + g) * 36 + s * 8 + tg;
            unsigned ah[4] = {Qh[abase], Qh[abase + 8 * 36], Qh[abase + 4], Qh[abase + 8 * 36 + 4]};
            unsigned al[4] = {Ql[abase], Ql[abase + 8 * 36], Ql[abase + 4], Ql[abase + 8 * 36 + 4]};
#pragma unroll
            for (int nf = 0; nf < 4; nf++) {
                int n = wn * 32 + nf * 8 + g;
                unsigned bhf[2] = {Kh[(s * 8 + tg) * 72 + n], Kh[(s * 8 + tg + 4) * 72 + n]};
                unsigned blf[2] = {Kl[(s * 8 + tg) * 72 + n], Kl[(s * 8 + tg + 4) * 72 + n]};
                mma_f16(acc[c][nf], ah, bhf);
                mma_f16(acc[c][nf], ah, blf);
                mma_f16(acc[c][nf], al, bhf);
            }
        }
    }

    // mask invalid columns (only last chunk can exceed N_)
#pragma unroll
    for (int nf = 0; nf < 4; nf++) {
        int col = 192 + wn * 32 + nf * 8 + 2 * tg;
        if (col >= N_)     { acc[3][nf][0] = -1e30f; acc[3][nf][2] = -1e30f; }
        if (col + 1 >= N_) { acc[3][nf][1] = -1e30f; acc[3][nf][3] = -1e30f; }
    }

    int lr0 = wm * 16 + g, lr1 = lr0 + 8;
    float mx0 = -1e30f, mx1 = -1e30f;
#pragma unroll
    for (int c = 0; c < 4; c++)
#pragma unroll
        for (int nf = 0; nf < 4; nf++) {
            mx0 = fmaxf(mx0, fmaxf(acc[c][nf][0], acc[c][nf][1]));
            mx1 = fmaxf(mx1, fmaxf(acc[c][nf][2], acc[c][nf][3]));
        }
    mx0 = fmaxf(mx0, __shfl_xor_sync(0xffffffffu, mx0, 1));
    mx0 = fmaxf(mx0, __shfl_xor_sync(0xffffffffu, mx0, 2));
    mx1 = fmaxf(mx1, __shfl_xor_sync(0xffffffffu, mx1, 1));
    mx1 = fmaxf(mx1, __shfl_xor_sync(0xffffffffu, mx1, 2));
    if (tg == 0) { red[0][wn][lr0] = mx0; red[0][wn][lr1] = mx1; }
    __syncthreads();
    mx0 = fmaxf(red[0][0][lr0], red[0][1][lr0]);
    mx1 = fmaxf(red[0][0][lr1], red[0][1][lr1]);

    float s0 = 0.f, s1 = 0.f;
#pragma unroll
    for (int c = 0; c < 4; c++)
#pragma unroll
        for (int nf = 0; nf < 4; nf++) {
            float e0 = expf(acc[c][nf][0] - mx0);
            float e1 = expf(acc[c][nf][1] - mx0);
            float e2 = expf(acc[c][nf][2] - mx1);
            float e3 = expf(acc[c][nf][3] - mx1);
            acc[c][nf][0] = e0; acc[c][nf][1] = e1;
            acc[c][nf][2] = e2; acc[c][nf][3] = e3;
            s0 += e0 + e1; s1 += e2 + e3;
        }
    s0 += __shfl_xor_sync(0xffffffffu, s0, 1);
    s0 += __shfl_xor_sync(0xffffffffu, s0, 2);
    s1 += __shfl_xor_sync(0xffffffffu, s1, 1);
    s1 += __shfl_xor_sync(0xffffffffu, s1, 2);
    if (tg == 0) { red[1][wn][lr0] = s0; red[1][wn][lr1] = s1; }
    __syncthreads();
    float inv0 = 1.f / (red[1][0][lr0] + red[1][1][lr0]);
    float inv1 = 1.f / (red[1][0][lr1] + red[1][1][lr1]);

    int row0 = m0 + lr0, row1 = m0 + lr1;
    unsigned* hout = (unsigned*)attnh;
#pragma unroll
    for (int c = 0; c < 4; c++)
#pragma unroll
        for (int nf = 0; nf < 4; nf++) {
            int col = c * 64 + wn * 32 + nf * 8 + 2 * tg;
            float v00 = acc[c][nf][0] * inv0, v01 = acc[c][nf][1] * inv0;
            float v10 = acc[c][nf][2] * inv1, v11 = acc[c][nf][3] * inv1;
            if (row0 < N_) {
                float* ar = attn + ((size_t)bh * N_ + row0) * N_;
                if (col < N_)     ar[col]     = v00;
                if (col + 1 < N_) ar[col + 1] = v01;
            }
            if (row1 < N_) {
                float* ar = attn + ((size_t)bh * N_ + row1) * N_;
                if (col < N_)     ar[col]     = v10;
                if (col + 1 < N_) ar[col + 1] = v11;
            }
            if (col < 224) {
                hout[((size_t)bh * 256 + row0) * 112 + col / 2] = packh2(v00, v01);
                hout[((size_t)bh * 256 + row1) * 112 + col / 2] = packh2(v10, v11);
            }
        }
}

// ---------------- AV: plain-fp16 MMA, reads padded fp16 attn ----------------
__global__ void av_mma(const __half* __restrict__ attnh, const float* __restrict__ qkv,
                       unsigned* __restrict__ aoh)
{
    __shared__ unsigned As[64 * 20], Vs[32 * 72];
    int bh = blockIdx.x, b = bh / H_, hh = bh % H_;
    int m0 = blockIdx.y * 64;
    int tid = threadIdx.x, lane = tid & 31, wid = tid >> 5;
    int g = lane >> 2, tg = lane & 3;
    int wm = wid & 3, wn = wid >> 2;
    const unsigned* ain = (const unsigned*)attnh;

    float acc[4][4];
#pragma unroll
    for (int i = 0; i < 4; i++)
#pragma unroll
        for (int j = 0; j < 4; j++) acc[i][j] = 0.f;

    for (int k0 = 0; k0 < 224; k0 += 32) {
        __syncthreads();
        {
            int m = tid >> 2, kw4 = (tid & 3) * 4;
            const unsigned* src = ain + ((size_t)bh * 256 + m0 + m) * 112 + k0 / 2 + kw4;
            *(uint4*)&As[m * 20 + kw4] = *(const uint4*)src;
        }
#pragma unroll
        for (int r = 0; r < 4; r++) {
            int idx = tid + r * 256;
            int kw = idx >> 6, n = idx & 63;
            int t0 = k0 + 2 * kw;
            float v0 = 0.f, v1 = 0.f;
            if (t0 < N_)     v0 = qkv[(size_t)(b * N_ + t0) * 2304 + 1536 + hh * 64 + n];
            if (t0 + 1 < N_) v1 = qkv[(size_t)(b * N_ + t0 + 1) * 2304 + 1536 + hh * 64 + n];
            Vs[kw * 72 + n] = packh2(v0, v1);
        }
        __syncthreads();
#pragma unroll
        for (int s = 0; s < 2; s++) {
            int abase = (wm * 16 + g) * 20 + s * 8 + tg;
            unsigned ah[4] = {As[abase], As[abase + 8 * 20], As[abase + 4], As[abase + 8 * 20 + 4]};
#pragma unroll
            for (int nf = 0; nf < 4; nf++) {
                int n = wn * 32 + nf * 8 + g;
                unsigned bf[2] = {Vs[(s * 8 + tg) * 72 + n], Vs[(s * 8 + tg + 4) * 72 + n]};
                mma_f16(acc[nf], ah, bf);
            }
        }
    }
#pragma unroll
    for (int nf = 0; nf < 4; nf++) {
        int col = wn * 32 + nf * 8 + 2 * tg;
#pragma unroll
        for (int hf = 0; hf < 2; hf++) {
            int m = m0 + wm * 16 + g + hf * 8;
            if (m < N_)
                aoh[(size_t)(b * N_ + m) * 384 + (hh * 64 + col) / 2] =
                    packh2(acc[nf][hf * 2 + 0], acc[nf][hf * 2 + 1]);
        }
    }
}

// ---------------- selection ----------------
__global__ void select_kernel(const float* __restrict__ attn, int* __restrict__ ik,
                              int* __restrict__ ie)
{
    __shared__ float diag[196];
    __shared__ int kept[196];
    int b = blockIdx.x, tid = threadIdx.x;
    if (tid < 196) {
        float s = 0.f;
        for (int hh = 0; hh < H_; hh++)
            s += attn[((size_t)(b * H_ + hh) * N_ + (tid + 1)) * N_ + (tid + 1)];
        diag[tid] = s;
    }
    __syncthreads();
    if (tid < 196) {
        float di = diag[tid];
        int rank = 0;
        for (int j = 0; j < 196; j++) {
            float dj = diag[j];
            rank += (dj > di) || (dj == di && j < tid);
        }
        kept[tid] = (rank < NKEPT_) ? 1 : 0;
    }
    __syncthreads();
    if (tid < 196) {
        int mine = kept[tid];
        int pos = 0;
        for (int j = 0; j < tid; j++) pos += (kept[j] == mine);
        if (mine) ik[b * K_ + 1 + pos] = tid + 1;
        else      ie[b * R_ + pos]     = tid + 1;
    }
    if (tid == 0) ik[b * K_] = 0;
}

// ---------------- propagation ----------------
__global__ void propagate_kernel(const float* __restrict__ attn, const float* __restrict__ x1,
                                 const int* __restrict__ ikg, const int* __restrict__ ieg,
                                 float* __restrict__ x2)
{
    extern __shared__ float sm[];
    float* ws = sm;
    float* xe = sm + K_ * R_;
    __shared__ int ik[K_], ie[R_];
    __shared__ int cnt;
    int bh = blockIdx.x;
    int b = bh / H_, hh = bh % H_;
    int tid = threadIdx.x;
    if (tid < K_) ik[tid] = ikg[b * K_ + tid];
    if (tid < R_) ie[tid] = ieg[b * R_ + tid];
    __syncthreads();
    const float* ablk = attn + (size_t)bh * N_ * N_;
    for (int idx = tid; idx < K_ * R_; idx += 256) {
        int k = idx / R_, e = idx - k * R_;
        ws[idx] = ablk[(size_t)ik[k] * N_ + ie[e]];
    }
    for (int idx = tid; idx < R_ * 64; idx += 256) {
        int e = idx >> 6, d = idx & 63;
        xe[idx] = x1[(size_t)(b * N_ + ie[e]) * 768 + hh * 64 + d];
    }
    __syncthreads();

    unsigned lo = 0u, hi = 0x7f7fffffu;
    while (lo < hi) {
        unsigned mid = lo + ((hi - lo + 1) >> 1);
        if (tid == 0) cnt = 0;
        __syncthreads();
        int local = 0;
        for (int i = tid; i < K_ * R_; i += 256)
            local += (__float_as_uint(ws[i]) >= mid);
        for (int off = 16; off; off >>= 1) local += __shfl_xor_sync(0xffffffffu, local, off);
        if ((tid & 31) == 0) atomicAdd(&cnt, local);
        __syncthreads();
        int c = cnt;
        __syncthreads();
        if (c >= THRK_) lo = mid; else hi = mid - 1;
    }
    float thr = __uint_as_float(lo);

    for (int p = tid; p < K_ * 64; p += 256) {
        int k = p >> 6, d = p & 63;
        const float* wr = ws + k * R_;
        float acc = 0.f;
#pragma unroll 2
        for (int e = 0; e < R_; e++) {
            float wv = wr[e];
            wv = (wv >= thr) ? wv : 0.f;
            acc = fmaf(wv, xe[e * 64 + d], acc);
        }
        x2[(size_t)(b * K_ + k) * 768 + hh * 64 + d] =
            x1[(size_t)(b * N_ + ik[k]) * 768 + hh * 64 + d] + ALPHA_ * acc;
    }
}

// ---------------- host ----------------
extern "C" void kernel_launch(void* const* d_in, const int* in_sizes, int n_in,
                              void* d_out, int out_size)
{
    const float* x     = (const float*)d_in[0];
    const float* n1g   = (const float*)d_in[1];
    const float* n1b   = (const float*)d_in[2];
    const float* qkvw  = (const float*)d_in[3];
    const float* projw = (const float*)d_in[4];
    const float* projb = (const float*)d_in[5];
    const float* n2g   = (const float*)d_in[6];
    const float* n2b   = (const float*)d_in[7];
    const float* fc1w  = (const float*)d_in[8];
    const float* fc1b  = (const float*)d_in[9];
    const float* fc2w  = (const float*)d_in[10];
    const float* fc2b  = (const float*)d_in[11];
    float* out = (float*)d_out;

    float *qkv, *attn, *x1, *x2;
    int *ik, *ie;
    unsigned *hh, *hl, *aoh, *h2h, *mlph;
    __half *wqkvh, *wqkvl, *wprojh, *wfc1h, *wfc2h, *attnh;
    cudaGetSymbolAddress((void**)&qkv,  g_qkv);
    cudaGetSymbolAddress((void**)&attn, g_attn);
    cudaGetSymbolAddress((void**)&attnh, g_attnh);
    cudaGetSymbolAddress((void**)&x1,   g_x1);
    cudaGetSymbolAddress((void**)&x2,   g_x2);
    cudaGetSymbolAddress((void**)&ik,   g_ik);
    cudaGetSymbolAddress((void**)&ie,   g_ie);
    cudaGetSymbolAddress((void**)&hh,   g_hh);
    cudaGetSymbolAddress((void**)&hl,   g_hl);
    cudaGetSymbolAddress((void**)&wqkvh, g_wqkvh);
    cudaGetSymbolAddress((void**)&wqkvl, g_wqkvl);
    cudaGetSymbolAddress((void**)&wprojh, g_wprojh);
    cudaGetSymbolAddress((void**)&wfc1h, g_wfc1h);
    cudaGetSymbolAddress((void**)&wfc2h, g_wfc2h);
    cudaGetSymbolAddress((void**)&aoh,  g_aoh);
    cudaGetSymbolAddress((void**)&h2h,  g_h2h);
    cudaGetSymbolAddress((void**)&mlph, g_mlph);

    const int PROP_SMEM = (K_ * R_ + R_ * 64) * 4;
    cudaFuncSetAttribute(propagate_kernel, cudaFuncAttributeMaxDynamicSharedMemorySize, PROP_SMEM);
    const int SMEM_PLAIN = (ABUF + BBUF) * 2 * 2;
    const int SMEM_SPLIT = (ABUF + BBUF) * 4 * 2;
    cudaFuncSetAttribute(hgemm_kernel<1, false, false, false, false>,
                         cudaFuncAttributeMaxDynamicSharedMemorySize, SMEM_SPLIT);
    cudaFuncSetAttribute(hgemm_kernel<0, false, false, false, false>,
                         cudaFuncAttributeMaxDynamicSharedMemorySize, SMEM_PLAIN);
    cudaFuncSetAttribute(hgemm_kernel<0, false, true, true, false>,
                         cudaFuncAttributeMaxDynamicSharedMemorySize, SMEM_PLAIN);
    cudaFuncSetAttribute(hgemm_kernel<0, true, true, false, true>,
                         cudaFuncAttributeMaxDynamicSharedMemorySize, SMEM_PLAIN);

    // 0. weight conversion
    cvtw_h<1><<<(768 * 2304) / 2048, 256>>>(qkvw, wqkvh, wqkvl, 768 * 2304);
    cvtw_h<0><<<(768 * 768) / 2048, 256>>>(projw, wprojh, nullptr, 768 * 768);
    cvtw_h<0><<<(768 * 3072) / 2048, 256>>>(fc1w, wfc1h, nullptr, 768 * 3072);
    cvtw_h<0><<<(3072 * 768) / 2048, 256>>>(fc2w, wfc2h, nullptr, 3072 * 768);

    // 1. LN1 -> packed fp16 hi/lo
    ln_pack_kernel<1><<<B_ * N_, 256>>>(x, n1g, n1b, hh, hl);
    // 2a. QK columns [0,1536) split-fp16 (rank-safe)
    hgemm_kernel<1, false, false, false, false><<<dim3(6, 197), 256, SMEM_SPLIT>>>(
        hh, hl, wqkvh, wqkvl, nullptr, nullptr, qkv, nullptr, 2304, C_, 2304, 0);
    // 2b. V columns [1536,2304) plain fp16
    hgemm_kernel<0, false, false, false, false><<<dim3(3, 197), 256, SMEM_PLAIN>>>(
        hh, nullptr, wqkvh, nullptr, nullptr, nullptr, qkv, nullptr, 2304, C_, 2304, 1536);
    // 3. fused scores + softmax -> fp32 attn + padded fp16 attnh
    fsm_kernel<<<dim3(BH_, 4), 256>>>(qkv, attn, attnh);
    // 4. attn @ V (fp16 MMA) -> packed fp16 ao
    av_mma<<<dim3(BH_, 4), 256>>>(attnh, qkv, aoh);
    // 5. proj + bias + residual
    hgemm_kernel<0, false, true, true, false><<<dim3(3, 197), 256, SMEM_PLAIN>>>(
        aoh, nullptr, wprojh, nullptr, projb, x, x1, nullptr, C_, C_, C_, 0);
    // 6. selection
    select_kernel<<<B_, 256>>>(attn, ik, ie);
    // 7. propagation
    propagate_kernel<<<BH_, 256, PROP_SMEM>>>(attn, x1, ik, ie, x2);
    // 8. LN2 -> packed fp16
    ln_pack_kernel<0><<<B_ * K_, 256>>>(x2, n2g, n2b, h2h, nullptr);
    // 9. fc1 + gelu -> packed fp16
    hgemm_kernel<0, true, true, false, true><<<dim3(12, 99), 256, SMEM_PLAIN>>>(
        h2h, nullptr, wfc1h, nullptr, fc1b, nullptr, nullptr, mlph, 4 * C_, C_, 0, 0);
    // 10. fc2 + residual -> out
    hgemm_kernel<0, false, true, true, false><<<dim3(3, 99), 256, SMEM_PLAIN>>>(
        mlph, nullptr, wfc2h, nullptr, fc2b, x2, out, nullptr, C_, 4 * C_, C_, 0);
}

// round 12
// speedup vs baseline: 1.1194x; 1.1194x over previous
#include <cuda_runtime.h>
#include <cuda_fp16.h>
#include <math.h>

#define B_   64
#define N_   197
#define C_   768
#define H_   12
#define R_   98
#define K_   99
#define NKEPT_ 98
#define THRK_ 1941
#define ALPHA_ 0.1f
#define EPS_ 1e-5f
#define BH_  (B_*H_)
#define NP_  224

// ---------------- scratch ----------------
__device__ float    g_attn[(size_t)BH_*N_*N_];
__device__ __half   g_attnh[(size_t)BH_*256*NP_];
__device__ float    g_x1  [(size_t)B_*N_*C_];
__device__ float    g_x2  [(size_t)B_*K_*C_];
__device__ int      g_ik  [B_*K_];
__device__ int      g_ie  [B_*R_];
__device__ unsigned g_hh  [(size_t)B_*N_*C_/2];
__device__ unsigned g_hl  [(size_t)B_*N_*C_/2];
__device__ __half   g_wqkvh[(size_t)C_*3*C_];
__device__ __half   g_wqkvl[(size_t)C_*3*C_];
__device__ __half   g_wprojh[(size_t)C_*C_];
__device__ __half   g_wfc1h[(size_t)C_*4*C_];
__device__ __half   g_wfc2h[(size_t)4*C_*C_];
// head-major attention operands (padded to 224 tokens; pad rows stay zero)
__device__ __half   g_qh[(size_t)BH_*NP_*64];
__device__ __half   g_ql[(size_t)BH_*NP_*64];
__device__ __half   g_kh[(size_t)BH_*NP_*64];
__device__ __half   g_kl[(size_t)BH_*NP_*64];
__device__ __half   g_vh[(size_t)B_*NP_*C_];
__device__ unsigned g_aoh [(size_t)B_*N_*C_/2];
__device__ unsigned g_h2h [(size_t)B_*K_*C_/2];
__device__ unsigned g_mlph[(size_t)B_*K_*4*C_/2];

// ---------------- helpers ----------------
__device__ __forceinline__ unsigned packh2(float a, float b) {
    __half2 h = __floats2half2_rn(a, b);
    return *reinterpret_cast<unsigned*>(&h);
}
__device__ __forceinline__ void splith2(float a, float b, unsigned& hi, unsigned& lo) {
    __half ah = __float2half_rn(a), bh = __float2half_rn(b);
    __half2 h = __halves2half2(ah, bh);
    hi = *reinterpret_cast<unsigned*>(&h);
    lo = packh2(a - __half2float(ah), b - __half2float(bh));
}
__device__ __forceinline__ unsigned sm_u32(const void* p) {
    return (unsigned)__cvta_generic_to_shared(p);
}
__device__ __forceinline__ void ldsm4(unsigned r[4], unsigned a) {
    asm volatile("ldmatrix.sync.aligned.m8n8.x4.shared.b16 {%0,%1,%2,%3}, [%4];"
                 : "=r"(r[0]), "=r"(r[1]), "=r"(r[2]), "=r"(r[3]) : "r"(a));
}
__device__ __forceinline__ void ldsm4t(unsigned r[4], unsigned a) {
    asm volatile("ldmatrix.sync.aligned.m8n8.x4.trans.shared.b16 {%0,%1,%2,%3}, [%4];"
                 : "=r"(r[0]), "=r"(r[1]), "=r"(r[2]), "=r"(r[3]) : "r"(a));
}
__device__ __forceinline__ void mma_f16(float c[4], const unsigned a[4], const unsigned b[2]) {
    asm volatile(
        "mma.sync.aligned.m16n8k16.row.col.f32.f16.f16.f32 "
        "{%0,%1,%2,%3},{%4,%5,%6,%7},{%8,%9},{%0,%1,%2,%3};"
        : "+f"(c[0]), "+f"(c[1]), "+f"(c[2]), "+f"(c[3])
        : "r"(a[0]), "r"(a[1]), "r"(a[2]), "r"(a[3]), "r"(b[0]), "r"(b[1]));
}

// ---------------- weight convert ----------------
template<int SPLIT>
__global__ void cvtw_h(const float* __restrict__ w, __half* __restrict__ hi,
                       __half* __restrict__ lo, int n)
{
    int i = (blockIdx.x * 256 + threadIdx.x) * 8;
    if (i >= n) return;
    float4 a = *(const float4*)&w[i];
    float4 b = *(const float4*)&w[i + 4];
    __half2 h[4];
    h[0] = __floats2half2_rn(a.x, a.y); h[1] = __floats2half2_rn(a.z, a.w);
    h[2] = __floats2half2_rn(b.x, b.y); h[3] = __floats2half2_rn(b.z, b.w);
    *(uint4*)&hi[i] = *(uint4*)h;
    if (SPLIT) {
        __half2 l[4];
        l[0] = __floats2half2_rn(a.x - __low2float(h[0]), a.y - __high2float(h[0]));
        l[1] = __floats2half2_rn(a.z - __low2float(h[1]), a.w - __high2float(h[1]));
        l[2] = __floats2half2_rn(b.x - __low2float(h[2]), b.y - __high2float(h[2]));
        l[3] = __floats2half2_rn(b.z - __low2float(h[3]), b.w - __high2float(h[3]));
        *(uint4*)&lo[i] = *(uint4*)l;
    }
}

// ---------------- LayerNorm -> packed fp16 hi(/lo) ----------------
template<int SPLIT>
__global__ void ln_pack_kernel(const float* __restrict__ x, const float* __restrict__ g,
                               const float* __restrict__ bta,
                               unsigned* __restrict__ hi, unsigned* __restrict__ lo)
{
    int row = blockIdx.x;
    const float2* xr = (const float2*)(x + (size_t)row * C_);
    int tid = threadIdx.x;
    float2 v1 = xr[tid];
    float2 v2 = make_float2(0.f, 0.f);
    if (tid < 128) v2 = xr[tid + 256];
    float s = v1.x + v1.y + v2.x + v2.y;
    float ss = v1.x * v1.x + v1.y * v1.y + v2.x * v2.x + v2.y * v2.y;
    for (int off = 16; off; off >>= 1) {
        s  += __shfl_xor_sync(0xffffffffu, s, off);
        ss += __shfl_xor_sync(0xffffffffu, ss, off);
    }
    __shared__ float rs[8], rss[8];
    __shared__ float smean, srstd;
    int w = tid >> 5;
    if ((tid & 31) == 0) { rs[w] = s; rss[w] = ss; }
    __syncthreads();
    if (tid == 0) {
        float S = 0.f, SS = 0.f;
        for (int i = 0; i < 8; i++) { S += rs[i]; SS += rss[i]; }
        float mean = S * (1.f / C_);
        float var = SS * (1.f / C_) - mean * mean;
        smean = mean; srstd = rsqrtf(var + EPS_);
    }
    __syncthreads();
    float mean = smean, rstd = srstd;
    size_t base = (size_t)row * (C_ / 2);
#pragma unroll
    for (int p = 0; p < 2; p++) {
        if (p == 1 && tid >= 128) break;
        int wi = tid + p * 256;
        float2 v = (p == 0) ? v1 : v2;
        int c = wi * 2;
        float a = (v.x - mean) * rstd * g[c] + bta[c];
        float b = (v.y - mean) * rstd * g[c + 1] + bta[c + 1];
        if (SPLIT) { unsigned h, l; splith2(a, b, h, l); hi[base + wi] = h; lo[base + wi] = l; }
        else hi[base + wi] = packh2(a, b);
    }
}

// ---------------- fp16 GEMM: 64x256 tile, k32 steps, ldmatrix, double-buffered ----
// EPI: 0 = bias+res -> float; 1 = bias+gelu -> packed half; 2 = QK split head-major; 3 = V head-major
#define AST 40
#define BST 264
#define ABUF (64 * AST)
#define BBUF (32 * BST)

template<int SPLIT>
__device__ __forceinline__ void hg_compute(const __half* buf, const int aoff[2],
                                           const int boff[4], float acc[2][8][4])
{
    const __half* AsH = buf;
    const __half* AsL = buf + ABUF;
    const __half* BsH = buf + ABUF * (1 + SPLIT);
    const __half* BsL = BsH + BBUF;
#pragma unroll
    for (int s = 0; s < 2; s++) {
        unsigned ah[2][4], al[2][4];
#pragma unroll
        for (int mf = 0; mf < 2; mf++) {
            ldsm4(ah[mf], sm_u32(AsH + aoff[mf] + s * 16));
            if (SPLIT) ldsm4(al[mf], sm_u32(AsL + aoff[mf] + s * 16));
        }
        unsigned bhf[8][2], blf[8][2];
#pragma unroll
        for (int p = 0; p < 4; p++) {
            unsigned r[4];
            ldsm4t(r, sm_u32(BsH + boff[p] + s * 16 * BST));
            bhf[2*p][0] = r[0]; bhf[2*p][1] = r[1];
            bhf[2*p+1][0] = r[2]; bhf[2*p+1][1] = r[3];
            if (SPLIT) {
                unsigned rl[4];
                ldsm4t(rl, sm_u32(BsL + boff[p] + s * 16 * BST));
                blf[2*p][0] = rl[0]; blf[2*p][1] = rl[1];
                blf[2*p+1][0] = rl[2]; blf[2*p+1][1] = rl[3];
            }
        }
#pragma unroll
        for (int mf = 0; mf < 2; mf++)
#pragma unroll
            for (int nf = 0; nf < 8; nf++) {
                mma_f16(acc[mf][nf], ah[mf], bhf[nf]);
                if (SPLIT) {
                    mma_f16(acc[mf][nf], ah[mf], blf[nf]);
                    mma_f16(acc[mf][nf], al[mf], bhf[nf]);
                }
            }
    }
}

template<int SPLIT, int EPI>
__global__ void __launch_bounds__(256, 2)
hgemm_kernel(const unsigned* __restrict__ Ah, const unsigned* __restrict__ Al,
             const __half* __restrict__ Bh, const __half* __restrict__ Bl,
             const float* __restrict__ bias, const float* __restrict__ res,
             float* __restrict__ Cf, unsigned* __restrict__ Cu,
             unsigned* __restrict__ qh, unsigned* __restrict__ ql,
             unsigned* __restrict__ kh, unsigned* __restrict__ kl,
             unsigned* __restrict__ vh,
             int Nd, int Kd, int ldc, int n0ofs)
{
    extern __shared__ __half sh[];
    const int UNIT = (ABUF + BBUF) * (1 + SPLIT);
    int tid = threadIdx.x, lane = tid & 31, wid = tid >> 5;
    int wm = wid & 1, wn = wid >> 1;
    int g = lane >> 2, tg = lane & 3;
    int m0 = blockIdx.y * 64, n0 = blockIdx.x * 256 + n0ofs;
    int Kw = Kd / 2;

    float acc[2][8][4];
#pragma unroll
    for (int i = 0; i < 2; i++)
#pragma unroll
        for (int j = 0; j < 8; j++)
#pragma unroll
            for (int q = 0; q < 4; q++) acc[i][j][q] = 0.f;

    int ar = tid >> 2;
    int bkr = tid >> 5, bn8 = (tid & 31) * 8;
    const unsigned* ApH = Ah + (size_t)(m0 + ar) * Kw + (tid & 3) * 4;
    const unsigned* ApL = SPLIT ? Al + (size_t)(m0 + ar) * Kw + (tid & 3) * 4 : ApH;
    const __half* BpH = Bh + (size_t)bkr * Nd + n0 + bn8;
    const __half* BpL = SPLIT ? Bl + (size_t)bkr * Nd + n0 + bn8 : BpH;

    int aSts = ar * AST + (tid & 3) * 8;
    int bSts = bkr * BST + bn8;

    int aoff[2], boff[4];
#pragma unroll
    for (int mf = 0; mf < 2; mf++)
        aoff[mf] = (wm * 32 + mf * 16 + (lane & 15)) * AST + (lane >> 4) * 8;
#pragma unroll
    for (int p = 0; p < 4; p++)
        boff[p] = (lane & 15) * BST + wn * 64 + p * 16 + (lane >> 4) * 8;

    uint4 rah, ral, rbh[4], rbl[4];
    rah = *(const uint4*)ApH;
    if (SPLIT) ral = *(const uint4*)ApL;
#pragma unroll
    for (int j = 0; j < 4; j++) {
        rbh[j] = *(const uint4*)(BpH + (size_t)j * 8 * Nd);
        if (SPLIT) rbl[j] = *(const uint4*)(BpL + (size_t)j * 8 * Nd);
    }
    {
        __half* buf = sh;
        *(uint4*)&buf[aSts] = rah;
        if (SPLIT) *(uint4*)&buf[ABUF + aSts] = ral;
        __half* bb = buf + ABUF * (1 + SPLIT);
#pragma unroll
        for (int j = 0; j < 4; j++) {
            *(uint4*)&bb[bSts + j * 8 * BST] = rbh[j];
            if (SPLIT) *(uint4*)&bb[BBUF + bSts + j * 8 * BST] = rbl[j];
        }
    }
    __syncthreads();

    int nit = Kd / 32;
    for (int it = 1; it < nit; it++) {
        rah = *(const uint4*)(ApH + it * 16);
        if (SPLIT) ral = *(const uint4*)(ApL + it * 16);
#pragma unroll
        for (int j = 0; j < 4; j++) {
            rbh[j] = *(const uint4*)(BpH + (size_t)(it * 32 + j * 8) * Nd);
            if (SPLIT) rbl[j] = *(const uint4*)(BpL + (size_t)(it * 32 + j * 8) * Nd);
        }
        hg_compute<SPLIT>(sh + ((it - 1) & 1) * UNIT, aoff, boff, acc);
        {
            __half* buf = sh + (it & 1) * UNIT;
            *(uint4*)&buf[aSts] = rah;
            if (SPLIT) *(uint4*)&buf[ABUF + aSts] = ral;
            __half* bb = buf + ABUF * (1 + SPLIT);
#pragma unroll
            for (int j = 0; j < 4; j++) {
                *(uint4*)&bb[bSts + j * 8 * BST] = rbh[j];
                if (SPLIT) *(uint4*)&bb[BBUF + bSts + j * 8 * BST] = rbl[j];
            }
        }
        __syncthreads();
    }
    hg_compute<SPLIT>(sh + ((nit - 1) & 1) * UNIT, aoff, boff, acc);

    // epilogue
#pragma unroll
    for (int mf = 0; mf < 2; mf++) {
        int row = m0 + wm * 32 + mf * 16 + g;
#pragma unroll
        for (int nf = 0; nf < 8; nf++) {
            int col = n0 + wn * 64 + nf * 8 + 2 * tg;
            float b0 = 0.f, b1 = 0.f;
            if (EPI == 0 || EPI == 1) { b0 = bias[col]; b1 = bias[col + 1]; }
#pragma unroll
            for (int half = 0; half < 2; half++) {
                int r = row + half * 8;
                float c0 = acc[mf][nf][half * 2 + 0] + b0;
                float c1 = acc[mf][nf][half * 2 + 1] + b1;
                if (EPI == 0) {
                    size_t base = (size_t)r * ldc + col;
                    float2 rv = *(const float2*)&res[base];
                    float2 ov; ov.x = c0 + rv.x; ov.y = c1 + rv.y;
                    *(float2*)&Cf[base] = ov;
                } else if (EPI == 1) {
                    c0 = 0.5f * c0 * (1.f + erff(c0 * 0.70710678118654752f));
                    c1 = 0.5f * c1 * (1.f + erff(c1 * 0.70710678118654752f));
                    Cu[(size_t)r * (Nd / 2) + col / 2] = packh2(c0, c1);
                } else if (EPI == 2) {
                    int b = r / N_, m = r - b * N_;
                    int part = col >= 768;
                    int rem = col - (part ? 768 : 0);
                    int hd = rem >> 6, d = rem & 63;
                    float s0 = c0, s1 = c1;
                    if (!part) { s0 *= 0.125f; s1 *= 0.125f; }
                    unsigned h, l;
                    splith2(s0, s1, h, l);
                    size_t o = ((size_t)(b * H_ + hd) * NP_ + m) * 32 + (d >> 1);
                    (part ? kh : qh)[o] = h;
                    (part ? kl : ql)[o] = l;
                } else {
                    int b = r / N_, m = r - b * N_;
                    int cv = col - 1536;
                    vh[((size_t)b * NP_ + m) * 384 + (cv >> 1)] = packh2(c0, c1);
                }
            }
        }
    }
}

// ---------------- fused scores + softmax (reads pre-split fp16 Q/K) ----------------
__global__ void fsm_kernel(const __half* __restrict__ qhg, const __half* __restrict__ qlg,
                           const __half* __restrict__ khg, const __half* __restrict__ klg,
                           float* __restrict__ attn, __half* __restrict__ attnh)
{
    __shared__ unsigned Qh[64 * 36], Ql[64 * 36], Kh[32 * 73], Kl[32 * 73];
    __shared__ float red[2][2][64];
    int bh = blockIdx.x;
    int m0 = blockIdx.y * 64;
    int tid = threadIdx.x, lane = tid & 31, wid = tid >> 5;
    int g = lane >> 2, tg = lane & 3;
    int wm = wid & 3, wn = wid >> 2;
    const unsigned* qhw = (const unsigned*)qhg;
    const unsigned* qlw = (const unsigned*)qlg;
    const unsigned* khw = (const unsigned*)khg;
    const unsigned* klw = (const unsigned*)klg;

    // Q tile: direct copy (64 rows x 32 words), padded rows are zero
#pragma unroll
    for (int r = 0; r < 2; r++) {
        int idx = tid + r * 256;
        int row = idx >> 3, w4 = (idx & 7) * 4;
        size_t src = ((size_t)bh * NP_ + m0 + row) * 32 + w4;
        *(uint4*)&Qh[row * 36 + w4] = *(const uint4*)&qhw[src];
        *(uint4*)&Ql[row * 36 + w4] = *(const uint4*)&qlw[src];
    }

    float acc[4][4][4];
#pragma unroll
    for (int c = 0; c < 4; c++)
#pragma unroll
        for (int j = 0; j < 4; j++)
#pragma unroll
            for (int q = 0; q < 4; q++) acc[c][j][q] = 0.f;

    for (int c = 0; c < 4; c++) {
        int n0 = c * 64;
        __syncthreads();
        // K tile: transpose on load into [word-row][token], stride 73
#pragma unroll
        for (int r = 0; r < 2; r++) {
            int idx = tid + r * 256;
            int token = idx >> 3, wp = idx & 7;
            uint4 vh4 = make_uint4(0u, 0u, 0u, 0u), vl4 = make_uint4(0u, 0u, 0u, 0u);
            if (n0 + token < NP_) {
                size_t src = ((size_t)bh * NP_ + n0 + token) * 32 + wp * 4;
                vh4 = *(const uint4*)&khw[src];
                vl4 = *(const uint4*)&klw[src];
            }
            Kh[(wp * 4 + 0) * 73 + token] = vh4.x;
            Kh[(wp * 4 + 1) * 73 + token] = vh4.y;
            Kh[(wp * 4 + 2) * 73 + token] = vh4.z;
            Kh[(wp * 4 + 3) * 73 + token] = vh4.w;
            Kl[(wp * 4 + 0) * 73 + token] = vl4.x;
            Kl[(wp * 4 + 1) * 73 + token] = vl4.y;
            Kl[(wp * 4 + 2) * 73 + token] = vl4.z;
            Kl[(wp * 4 + 3) * 73 + token] = vl4.w;
        }
        __syncthreads();
#pragma unroll
        for (int s = 0; s < 4; s++) {
            int abase = (wm * 16 + g) * 36 + s * 8 + tg;
            unsigned ah[4] = {Qh[abase], Qh[abase + 8 * 36], Qh[abase + 4], Qh[abase + 8 * 36 + 4]};
            unsigned al[4] = {Ql[abase], Ql[abase + 8 * 36], Ql[abase + 4], Ql[abase + 8 * 36 + 4]};
#pragma unroll
            for (int nf = 0; nf < 4; nf++) {
                int n = wn * 32 + nf * 8 + g;
                unsigned bhf[2] = {Kh[(s * 8 + tg) * 73 + n], Kh[(s * 8 + tg + 4) * 73 + n]};
                unsigned blf[2] = {Kl[(s * 8 + tg) * 73 + n], Kl[(s * 8 + tg + 4) * 73 + n]};
                mma_f16(acc[c][nf], ah, bhf);
                mma_f16(acc[c][nf], ah, blf);
                mma_f16(acc[c][nf], al, bhf);
            }
        }
    }

    // mask invalid columns (chunk 3 covers cols 192..255)
#pragma unroll
    for (int nf = 0; nf < 4; nf++) {
        int col = 192 + wn * 32 + nf * 8 + 2 * tg;
        if (col >= N_)     { acc[3][nf][0] = -1e30f; acc[3][nf][2] = -1e30f; }
        if (col + 1 >= N_) { acc[3][nf][1] = -1e30f; acc[3][nf][3] = -1e30f; }
    }

    int lr0 = wm * 16 + g, lr1 = lr0 + 8;
    float mx0 = -1e30f, mx1 = -1e30f;
#pragma unroll
    for (int c = 0; c < 4; c++)
#pragma unroll
        for (int nf = 0; nf < 4; nf++) {
            mx0 = fmaxf(mx0, fmaxf(acc[c][nf][0], acc[c][nf][1]));
            mx1 = fmaxf(mx1, fmaxf(acc[c][nf][2], acc[c][nf][3]));
        }
    mx0 = fmaxf(mx0, __shfl_xor_sync(0xffffffffu, mx0, 1));
    mx0 = fmaxf(mx0, __shfl_xor_sync(0xffffffffu, mx0, 2));
    mx1 = fmaxf(mx1, __shfl_xor_sync(0xffffffffu, mx1, 1));
    mx1 = fmaxf(mx1, __shfl_xor_sync(0xffffffffu, mx1, 2));
    if (tg == 0) { red[0][wn][lr0] = mx0; red[0][wn][lr1] = mx1; }
    __syncthreads();
    mx0 = fmaxf(red[0][0][lr0], red[0][1][lr0]);
    mx1 = fmaxf(red[0][0][lr1], red[0][1][lr1]);

    float s0 = 0.f, s1 = 0.f;
#pragma unroll
    for (int c = 0; c < 4; c++)
#pragma unroll
        for (int nf = 0; nf < 4; nf++) {
            float e0 = expf(acc[c][nf][0] - mx0);
            float e1 = expf(acc[c][nf][1] - mx0);
            float e2 = expf(acc[c][nf][2] - mx1);
            float e3 = expf(acc[c][nf][3] - mx1);
            acc[c][nf][0] = e0; acc[c][nf][1] = e1;
            acc[c][nf][2] = e2; acc[c][nf][3] = e3;
            s0 += e0 + e1; s1 += e2 + e3;
        }
    s0 += __shfl_xor_sync(0xffffffffu, s0, 1);
    s0 += __shfl_xor_sync(0xffffffffu, s0, 2);
    s1 += __shfl_xor_sync(0xffffffffu, s1, 1);
    s1 += __shfl_xor_sync(0xffffffffu, s1, 2);
    if (tg == 0) { red[1][wn][lr0] = s0; red[1][wn][lr1] = s1; }
    __syncthreads();
    float inv0 = 1.f / (red[1][0][lr0] + red[1][1][lr0]);
    float inv1 = 1.f / (red[1][0][lr1] + red[1][1][lr1]);

    int row0 = m0 + lr0, row1 = m0 + lr1;
    unsigned* hout = (unsigned*)attnh;
#pragma unroll
    for (int c = 0; c < 4; c++)
#pragma unroll
        for (int nf = 0; nf < 4; nf++) {
            int col = c * 64 + wn * 32 + nf * 8 + 2 * tg;
            float v00 = acc[c][nf][0] * inv0, v01 = acc[c][nf][1] * inv0;
            float v10 = acc[c][nf][2] * inv1, v11 = acc[c][nf][3] * inv1;
            if (row0 < N_) {
                float* ar = attn + ((size_t)bh * N_ + row0) * N_;
                if (col < N_)     ar[col]     = v00;
                if (col + 1 < N_) ar[col + 1] = v01;
            }
            if (row1 < N_) {
                float* ar = attn + ((size_t)bh * N_ + row1) * N_;
                if (col < N_)     ar[col]     = v10;
                if (col + 1 < N_) ar[col + 1] = v11;
            }
            if (col < NP_) {   // CRITICAL guard: chunk 3 cols reach 255 > 223
                hout[((size_t)bh * 256 + row0) * 112 + col / 2] = packh2(v00, v01);
                hout[((size_t)bh * 256 + row1) * 112 + col / 2] = packh2(v10, v11);
            }
        }
}

// ---------------- AV: all-fp16, ldmatrix both operands ----------------
__global__ void av_mma(const __half* __restrict__ attnh, const __half* __restrict__ vhg,
                       unsigned* __restrict__ aoh)
{
    __shared__ __half As[64 * 40], Vs[32 * 72];
    int bh = blockIdx.x, b = bh / H_, hh = bh % H_;
    int m0 = blockIdx.y * 64;
    int tid = threadIdx.x, lane = tid & 31, wid = tid >> 5;
    int g = lane >> 2, tg = lane & 3;
    int wm = wid & 3, wn = wid >> 2;
    const unsigned* ain = (const unsigned*)attnh;

    float acc[4][4];
#pragma unroll
    for (int i = 0; i < 4; i++)
#pragma unroll
        for (int j = 0; j < 4; j++) acc[i][j] = 0.f;

    int aoff = (wm * 16 + (lane & 15)) * 40 + (lane >> 4) * 8;
    int boff[2];
#pragma unroll
    for (int p = 0; p < 2; p++)
        boff[p] = (lane & 15) * 72 + wn * 32 + p * 16 + (lane >> 4) * 8;

    for (int k0 = 0; k0 < NP_; k0 += 32) {
        __syncthreads();
        {   // A: 64 rows x 32 halves from padded attnh
            int m = tid >> 2, kw4 = (tid & 3) * 4;
            const unsigned* src = ain + ((size_t)bh * 256 + m0 + m) * 112 + k0 / 2 + kw4;
            *(uint4*)&As[m * 40 + (tid & 3) * 8] = *(const uint4*)src;
        }
        {   // V: 32 token-rows x 64 halves from padded vh
            int token = tid >> 3, n8 = (tid & 7) * 8;
            const __half* src = vhg + ((size_t)b * NP_ + k0 + token) * C_ + hh * 64 + n8;
            *(uint4*)&Vs[token * 72 + n8] = *(const uint4*)src;
        }
        __syncthreads();
#pragma unroll
        for (int s = 0; s < 2; s++) {
            unsigned ah[4];
            ldsm4(ah, sm_u32(As + aoff + s * 16));
#pragma unroll
            for (int p = 0; p < 2; p++) {
                unsigned r[4];
                ldsm4t(r, sm_u32(Vs + boff[p] + s * 16 * 72));
                unsigned b0[2] = {r[0], r[1]}, b1[2] = {r[2], r[3]};
                mma_f16(acc[2*p],   ah, b0);
                mma_f16(acc[2*p+1], ah, b1);
            }
        }
    }
#pragma unroll
    for (int nf = 0; nf < 4; nf++) {
        int col = wn * 32 + nf * 8 + 2 * tg;
#pragma unroll
        for (int hf = 0; hf < 2; hf++) {
            int m = m0 + wm * 16 + g + hf * 8;
            if (m < N_)
                aoh[(size_t)(b * N_ + m) * 384 + (hh * 64 + col) / 2] =
                    packh2(acc[nf][hf * 2 + 0], acc[nf][hf * 2 + 1]);
        }
    }
}

// ---------------- selection ----------------
__global__ void select_kernel(const float* __restrict__ attn, int* __restrict__ ik,
                              int* __restrict__ ie)
{
    __shared__ float diag[196];
    __shared__ int kept[196];
    int b = blockIdx.x, tid = threadIdx.x;
    if (tid < 196) {
        float s = 0.f;
        for (int hh = 0; hh < H_; hh++)
            s += attn[((size_t)(b * H_ + hh) * N_ + (tid + 1)) * N_ + (tid + 1)];
        diag[tid] = s;
    }
    __syncthreads();
    if (tid < 196) {
        float di = diag[tid];
        int rank = 0;
        for (int j = 0; j < 196; j++) {
            float dj = diag[j];
            rank += (dj > di) || (dj == di && j < tid);
        }
        kept[tid] = (rank < NKEPT_) ? 1 : 0;
    }
    __syncthreads();
    if (tid < 196) {
        int mine = kept[tid];
        int pos = 0;
        for (int j = 0; j < tid; j++) pos += (kept[j] == mine);
        if (mine) ik[b * K_ + 1 + pos] = tid + 1;
        else      ie[b * R_ + pos]     = tid + 1;
    }
    if (tid == 0) ik[b * K_] = 0;
}

// ---------------- propagation: register-resident threshold search ----------------
#define PT_ 38
__global__ void propagate_kernel(const float* __restrict__ attn, const float* __restrict__ x1,
                                 const int* __restrict__ ikg, const int* __restrict__ ieg,
                                 float* __restrict__ x2)
{
    extern __shared__ float sm[];
    float* ws = sm;
    float* xe = sm + K_ * R_;
    __shared__ int ik[K_], ie[R_];
    __shared__ int cnt;
    int bh = blockIdx.x;
    int b = bh / H_, hh = bh % H_;
    int tid = threadIdx.x;
    if (tid < K_) ik[tid] = ikg[b * K_ + tid];
    if (tid < R_) ie[tid] = ieg[b * R_ + tid];
    __syncthreads();
    const float* ablk = attn + (size_t)bh * N_ * N_;
    unsigned uv[PT_];
#pragma unroll
    for (int j = 0; j < PT_; j++) {
        int idx = tid + j * 256;
        float w = 0.f;
        if (idx < K_ * R_) {
            int k = idx / R_, e = idx - k * R_;
            w = ablk[(size_t)ik[k] * N_ + ie[e]];
            ws[idx] = w;
        }
        uv[j] = __float_as_uint(w);
    }
    for (int idx = tid; idx < R_ * 64; idx += 256) {
        int e = idx >> 6, d = idx & 63;
        xe[idx] = x1[(size_t)(b * N_ + ie[e]) * 768 + hh * 64 + d];
    }
    __syncthreads();

    unsigned lo = 0u, hi = 0x3f801000u;   // softmax probs <= 1.0 (+ slack)
    while (lo < hi) {
        unsigned mid = lo + ((hi - lo + 1) >> 1);
        if (tid == 0) cnt = 0;
        __syncthreads();
        int local = 0;
#pragma unroll
        for (int j = 0; j < PT_; j++) local += (uv[j] >= mid);
        for (int off = 16; off; off >>= 1) local += __shfl_xor_sync(0xffffffffu, local, off);
        if ((tid & 31) == 0) atomicAdd(&cnt, local);
        __syncthreads();
        int c = cnt;
        __syncthreads();
        if (c >= THRK_) lo = mid; else hi = mid - 1;
    }
    float thr = __uint_as_float(lo);

    for (int p = tid; p < K_ * 64; p += 256) {
        int k = p >> 6, d = p & 63;
        const float* wr = ws + k * R_;
        float acc = 0.f;
#pragma unroll 2
        for (int e = 0; e < R_; e++) {
            float wv = wr[e];
            wv = (wv >= thr) ? wv : 0.f;
            acc = fmaf(wv, xe[e * 64 + d], acc);
        }
        x2[(size_t)(b * K_ + k) * 768 + hh * 64 + d] =
            x1[(size_t)(b * N_ + ik[k]) * 768 + hh * 64 + d] + ALPHA_ * acc;
    }
}

// ---------------- host ----------------
extern "C" void kernel_launch(void* const* d_in, const int* in_sizes, int n_in,
                              void* d_out, int out_size)
{
    const float* x     = (const float*)d_in[0];
    const float* n1g   = (const float*)d_in[1];
    const float* n1b   = (const float*)d_in[2];
    const float* qkvw  = (const float*)d_in[3];
    const float* projw = (const float*)d_in[4];
    const float* projb = (const float*)d_in[5];
    const float* n2g   = (const float*)d_in[6];
    const float* n2b   = (const float*)d_in[7];
    const float* fc1w  = (const float*)d_in[8];
    const float* fc1b  = (const float*)d_in[9];
    const float* fc2w  = (const float*)d_in[10];
    const float* fc2b  = (const float*)d_in[11];
    float* out = (float*)d_out;

    float *attn, *x1, *x2;
    int *ik, *ie;
    unsigned *hh, *hl, *aoh, *h2h, *mlph;
    __half *wqkvh, *wqkvl, *wprojh, *wfc1h, *wfc2h, *attnh, *qh, *ql, *kh, *kl, *vh;
    cudaGetSymbolAddress((void**)&attn, g_attn);
    cudaGetSymbolAddress((void**)&attnh, g_attnh);
    cudaGetSymbolAddress((void**)&x1,   g_x1);
    cudaGetSymbolAddress((void**)&x2,   g_x2);
    cudaGetSymbolAddress((void**)&ik,   g_ik);
    cudaGetSymbolAddress((void**)&ie,   g_ie);
    cudaGetSymbolAddress((void**)&hh,   g_hh);
    cudaGetSymbolAddress((void**)&hl,   g_hl);
    cudaGetSymbolAddress((void**)&wqkvh, g_wqkvh);
    cudaGetSymbolAddress((void**)&wqkvl, g_wqkvl);
    cudaGetSymbolAddress((void**)&wprojh, g_wprojh);
    cudaGetSymbolAddress((void**)&wfc1h, g_wfc1h);
    cudaGetSymbolAddress((void**)&wfc2h, g_wfc2h);
    cudaGetSymbolAddress((void**)&qh,   g_qh);
    cudaGetSymbolAddress((void**)&ql,   g_ql);
    cudaGetSymbolAddress((void**)&kh,   g_kh);
    cudaGetSymbolAddress((void**)&kl,   g_kl);
    cudaGetSymbolAddress((void**)&vh,   g_vh);
    cudaGetSymbolAddress((void**)&aoh,  g_aoh);
    cudaGetSymbolAddress((void**)&h2h,  g_h2h);
    cudaGetSymbolAddress((void**)&mlph, g_mlph);

    const int PROP_SMEM = (K_ * R_ + R_ * 64) * 4;
    cudaFuncSetAttribute(propagate_kernel, cudaFuncAttributeMaxDynamicSharedMemorySize, PROP_SMEM);
    const int SMEM_PLAIN = (ABUF + BBUF) * 2 * 2;
    const int SMEM_SPLIT = (ABUF + BBUF) * 4 * 2;
    cudaFuncSetAttribute(hgemm_kernel<1, 2>, cudaFuncAttributeMaxDynamicSharedMemorySize, SMEM_SPLIT);
    cudaFuncSetAttribute(hgemm_kernel<0, 3>, cudaFuncAttributeMaxDynamicSharedMemorySize, SMEM_PLAIN);
    cudaFuncSetAttribute(hgemm_kernel<0, 0>, cudaFuncAttributeMaxDynamicSharedMemorySize, SMEM_PLAIN);
    cudaFuncSetAttribute(hgemm_kernel<0, 1>, cudaFuncAttributeMaxDynamicSharedMemorySize, SMEM_PLAIN);

    // 0. weight conversion
    cvtw_h<1><<<(768 * 2304) / 2048, 256>>>(qkvw, wqkvh, wqkvl, 768 * 2304);
    cvtw_h<0><<<(768 * 768) / 2048, 256>>>(projw, wprojh, nullptr, 768 * 768);
    cvtw_h<0><<<(768 * 3072) / 2048, 256>>>(fc1w, wfc1h, nullptr, 768 * 3072);
    cvtw_h<0><<<(3072 * 768) / 2048, 256>>>(fc2w, wfc2h, nullptr, 3072 * 768);

    // 1. LN1 -> packed fp16 hi/lo
    ln_pack_kernel<1><<<B_ * N_, 256>>>(x, n1g, n1b, hh, hl);
    // 2a. QK (split) -> head-major split-fp16 q/k
    hgemm_kernel<1, 2><<<dim3(6, 197), 256, SMEM_SPLIT>>>(
        hh, hl, wqkvh, wqkvl, nullptr, nullptr, nullptr, nullptr,
        (unsigned*)qh, (unsigned*)ql, (unsigned*)kh, (unsigned*)kl, nullptr, 2304, C_, 0, 0);
    // 2b. V (plain) -> head-major fp16 v
    hgemm_kernel<0, 3><<<dim3(3, 197), 256, SMEM_PLAIN>>>(
        hh, nullptr, wqkvh, nullptr, nullptr, nullptr, nullptr, nullptr,
        nullptr, nullptr, nullptr, nullptr, (unsigned*)vh, 2304, C_, 0, 1536);
    // 3. fused scores + softmax
    fsm_kernel<<<dim3(BH_, 4), 256>>>(qh, ql, kh, kl, attn, attnh);
    // 4. attn @ V
    av_mma<<<dim3(BH_, 4), 256>>>(attnh, vh, aoh);
    // 5. proj + bias + residual
    hgemm_kernel<0, 0><<<dim3(3, 197), 256, SMEM_PLAIN>>>(
        aoh, nullptr, wprojh, nullptr, projb, x, x1, nullptr,
        nullptr, nullptr, nullptr, nullptr, nullptr, C_, C_, C_, 0);
    // 6. selection
    select_kernel<<<B_, 256>>>(attn, ik, ie);
    // 7. propagation
    propagate_kernel<<<BH_, 256, PROP_SMEM>>>(attn, x1, ik, ie, x2);
    // 8. LN2 -> packed fp16
    ln_pack_kernel<0><<<B_ * K_, 256>>>(x2, n2g, n2b, h2h, nullptr);
    // 9. fc1 + gelu -> packed fp16
    hgemm_kernel<0, 1><<<dim3(12, 99), 256, SMEM_PLAIN>>>(
        h2h, nullptr, wfc1h, nullptr, fc1b, nullptr, nullptr, mlph,
        nullptr, nullptr, nullptr, nullptr, nullptr, 4 * C_, C_, 0, 0);
    // 10. fc2 + residual -> out
    hgemm_kernel<0, 0><<<dim3(3, 99), 256, SMEM_PLAIN>>>(
        mlph, nullptr, wfc2h, nullptr, fc2b, x2, out, nullptr,
        nullptr, nullptr, nullptr, nullptr, nullptr, C_, 4 * C_, C_, 0);
}

// round 13
// speedup vs baseline: 1.1709x; 1.0460x over previous
#include <cuda_runtime.h>
#include <cuda_fp16.h>
#include <math.h>

#define B_   64
#define N_   197
#define C_   768
#define H_   12
#define R_   98
#define K_   99
#define NKEPT_ 98
#define THRK_ 1941
#define ALPHA_ 0.1f
#define EPS_ 1e-5f
#define BH_  (B_*H_)
#define NP_  224

// ---------------- scratch ----------------
__device__ __half   g_attnh[(size_t)BH_*256*NP_];
__device__ float    g_diag[(size_t)BH_*N_];
__device__ float    g_x1  [(size_t)B_*N_*C_];
__device__ float    g_x2  [(size_t)B_*K_*C_];
__device__ int      g_ik  [B_*K_];
__device__ int      g_ie  [B_*R_];
__device__ unsigned g_hh  [(size_t)B_*N_*C_/2];
__device__ unsigned g_hl  [(size_t)B_*N_*C_/2];
__device__ __half   g_wqkvh[(size_t)C_*3*C_];
__device__ __half   g_wqkvl[(size_t)C_*3*C_];
__device__ __half   g_wprojh[(size_t)C_*C_];
__device__ __half   g_wfc1h[(size_t)C_*4*C_];
__device__ __half   g_wfc2h[(size_t)4*C_*C_];
__device__ __half   g_qh[(size_t)BH_*NP_*64];
__device__ __half   g_ql[(size_t)BH_*NP_*64];
__device__ __half   g_kh[(size_t)BH_*NP_*64];
__device__ __half   g_kl[(size_t)BH_*NP_*64];
__device__ __half   g_vh[(size_t)B_*NP_*C_];
__device__ unsigned g_aoh [(size_t)B_*N_*C_/2];
__device__ unsigned g_h2h [(size_t)B_*K_*C_/2];
__device__ unsigned g_mlph[(size_t)B_*K_*4*C_/2];

// ---------------- helpers ----------------
__device__ __forceinline__ unsigned packh2(float a, float b) {
    __half2 h = __floats2half2_rn(a, b);
    return *reinterpret_cast<unsigned*>(&h);
}
__device__ __forceinline__ void splith2(float a, float b, unsigned& hi, unsigned& lo) {
    __half ah = __float2half_rn(a), bh = __float2half_rn(b);
    __half2 h = __halves2half2(ah, bh);
    hi = *reinterpret_cast<unsigned*>(&h);
    lo = packh2(a - __half2float(ah), b - __half2float(bh));
}
__device__ __forceinline__ unsigned sm_u32(const void* p) {
    return (unsigned)__cvta_generic_to_shared(p);
}
__device__ __forceinline__ void ldsm4(unsigned r[4], unsigned a) {
    asm volatile("ldmatrix.sync.aligned.m8n8.x4.shared.b16 {%0,%1,%2,%3}, [%4];"
                 : "=r"(r[0]), "=r"(r[1]), "=r"(r[2]), "=r"(r[3]) : "r"(a));
}
__device__ __forceinline__ void ldsm4t(unsigned r[4], unsigned a) {
    asm volatile("ldmatrix.sync.aligned.m8n8.x4.trans.shared.b16 {%0,%1,%2,%3}, [%4];"
                 : "=r"(r[0]), "=r"(r[1]), "=r"(r[2]), "=r"(r[3]) : "r"(a));
}
__device__ __forceinline__ void mma_f16(float c[4], const unsigned a[4], const unsigned b[2]) {
    asm volatile(
        "mma.sync.aligned.m16n8k16.row.col.f32.f16.f16.f32 "
        "{%0,%1,%2,%3},{%4,%5,%6,%7},{%8,%9},{%0,%1,%2,%3};"
        : "+f"(c[0]), "+f"(c[1]), "+f"(c[2]), "+f"(c[3])
        : "r"(a[0]), "r"(a[1]), "r"(a[2]), "r"(a[3]), "r"(b[0]), "r"(b[1]));
}

// ---------------- fused weight convert (all four weights, one launch) ----------
// segments in 8-float units
#define S0_ (768*2304/8)
#define S1_ (S0_ + 768*768/8)
#define S2_ (S1_ + 768*3072/8)
#define S3_ (S2_ + 3072*768/8)
__global__ void cvtw_all(const float* __restrict__ wqkv, const float* __restrict__ wproj,
                         const float* __restrict__ wfc1, const float* __restrict__ wfc2,
                         __half* __restrict__ qkvh, __half* __restrict__ qkvl,
                         __half* __restrict__ projh, __half* __restrict__ fc1h,
                         __half* __restrict__ fc2h)
{
    int i8 = blockIdx.x * 256 + threadIdx.x;
    if (i8 >= S3_) return;
    const float* src; __half* dsth; __half* dstl = nullptr; int base;
    if (i8 < S0_)      { src = wqkv;  dsth = qkvh;  dstl = qkvl; base = 0; }
    else if (i8 < S1_) { src = wproj; dsth = projh; base = S0_; }
    else if (i8 < S2_) { src = wfc1;  dsth = fc1h;  base = S1_; }
    else               { src = wfc2;  dsth = fc2h;  base = S2_; }
    int i = (i8 - base) * 8;
    float4 a = *(const float4*)&src[i];
    float4 b = *(const float4*)&src[i + 4];
    __half2 h[4];
    h[0] = __floats2half2_rn(a.x, a.y); h[1] = __floats2half2_rn(a.z, a.w);
    h[2] = __floats2half2_rn(b.x, b.y); h[3] = __floats2half2_rn(b.z, b.w);
    *(uint4*)&dsth[i] = *(uint4*)h;
    if (dstl) {
        __half2 l[4];
        l[0] = __floats2half2_rn(a.x - __low2float(h[0]), a.y - __high2float(h[0]));
        l[1] = __floats2half2_rn(a.z - __low2float(h[1]), a.w - __high2float(h[1]));
        l[2] = __floats2half2_rn(b.x - __low2float(h[2]), b.y - __high2float(h[2]));
        l[3] = __floats2half2_rn(b.z - __low2float(h[3]), b.w - __high2float(h[3]));
        *(uint4*)&dstl[i] = *(uint4*)l;
    }
}

// ---------------- LayerNorm -> packed fp16 hi(/lo) ----------------
template<int SPLIT>
__global__ void ln_pack_kernel(const float* __restrict__ x, const float* __restrict__ g,
                               const float* __restrict__ bta,
                               unsigned* __restrict__ hi, unsigned* __restrict__ lo)
{
    int row = blockIdx.x;
    const float2* xr = (const float2*)(x + (size_t)row * C_);
    int tid = threadIdx.x;
    float2 v1 = xr[tid];
    float2 v2 = make_float2(0.f, 0.f);
    if (tid < 128) v2 = xr[tid + 256];
    float s = v1.x + v1.y + v2.x + v2.y;
    float ss = v1.x * v1.x + v1.y * v1.y + v2.x * v2.x + v2.y * v2.y;
    for (int off = 16; off; off >>= 1) {
        s  += __shfl_xor_sync(0xffffffffu, s, off);
        ss += __shfl_xor_sync(0xffffffffu, ss, off);
    }
    __shared__ float rs[8], rss[8];
    __shared__ float smean, srstd;
    int w = tid >> 5;
    if ((tid & 31) == 0) { rs[w] = s; rss[w] = ss; }
    __syncthreads();
    if (tid == 0) {
        float S = 0.f, SS = 0.f;
        for (int i = 0; i < 8; i++) { S += rs[i]; SS += rss[i]; }
        float mean = S * (1.f / C_);
        float var = SS * (1.f / C_) - mean * mean;
        smean = mean; srstd = rsqrtf(var + EPS_);
    }
    __syncthreads();
    float mean = smean, rstd = srstd;
    size_t base = (size_t)row * (C_ / 2);
#pragma unroll
    for (int p = 0; p < 2; p++) {
        if (p == 1 && tid >= 128) break;
        int wi = tid + p * 256;
        float2 v = (p == 0) ? v1 : v2;
        int c = wi * 2;
        float a = (v.x - mean) * rstd * g[c] + bta[c];
        float b = (v.y - mean) * rstd * g[c + 1] + bta[c + 1];
        if (SPLIT) { unsigned h, l; splith2(a, b, h, l); hi[base + wi] = h; lo[base + wi] = l; }
        else hi[base + wi] = packh2(a, b);
    }
}

// ---------------- fp16 GEMM: 64xNT tile, k32 steps, ldmatrix, double-buffered ----
// EPI: 0 = bias+res -> float; 1 = bias+gelu -> packed half; 2 = QK split head-major; 3 = V head-major
#define AST 40
#define ABUF (64 * AST)

template<int SPLIT, int NT>
__device__ __forceinline__ void hg_compute(const __half* buf, const int aoff[2],
                                           const int* boff, float (*acc)[4])
{
    const int BSTc = NT + 8;
    const int BBUFc = 32 * BSTc;
    const int NF = NT / 32;
    const __half* AsH = buf;
    const __half* AsL = buf + ABUF;
    const __half* BsH = buf + ABUF * (1 + SPLIT);
    const __half* BsL = BsH + BBUFc;
#pragma unroll
    for (int s = 0; s < 2; s++) {
        unsigned ah[2][4], al[2][4];
#pragma unroll
        for (int mf = 0; mf < 2; mf++) {
            ldsm4(ah[mf], sm_u32(AsH + aoff[mf] + s * 16));
            if (SPLIT) ldsm4(al[mf], sm_u32(AsL + aoff[mf] + s * 16));
        }
        unsigned bhf[NF][2], blf[NF][2];
#pragma unroll
        for (int p = 0; p < NF / 2; p++) {
            unsigned r[4];
            ldsm4t(r, sm_u32(BsH + boff[p] + s * 16 * BSTc));
            bhf[2*p][0] = r[0]; bhf[2*p][1] = r[1];
            bhf[2*p+1][0] = r[2]; bhf[2*p+1][1] = r[3];
            if (SPLIT) {
                unsigned rl[4];
                ldsm4t(rl, sm_u32(BsL + boff[p] + s * 16 * BSTc));
                blf[2*p][0] = rl[0]; blf[2*p][1] = rl[1];
                blf[2*p+1][0] = rl[2]; blf[2*p+1][1] = rl[3];
            }
        }
#pragma unroll
        for (int mf = 0; mf < 2; mf++)
#pragma unroll
            for (int nf = 0; nf < NF; nf++) {
                mma_f16(acc[mf * NF + nf], ah[mf], bhf[nf]);
                if (SPLIT) {
                    mma_f16(acc[mf * NF + nf], ah[mf], blf[nf]);
                    mma_f16(acc[mf * NF + nf], al[mf], bhf[nf]);
                }
            }
    }
}

template<int SPLIT, int EPI, int NT>
__global__ void __launch_bounds__(256, 2)
hgemm_kernel(const unsigned* __restrict__ Ah, const unsigned* __restrict__ Al,
             const __half* __restrict__ Bh, const __half* __restrict__ Bl,
             const float* __restrict__ bias, const float* __restrict__ res,
             float* __restrict__ Cf, unsigned* __restrict__ Cu,
             unsigned* __restrict__ qh, unsigned* __restrict__ ql,
             unsigned* __restrict__ kh, unsigned* __restrict__ kl,
             unsigned* __restrict__ vh,
             int Nd, int Kd, int ldc, int n0ofs)
{
    extern __shared__ __half sh[];
    const int BSTc = NT + 8;
    const int BBUFc = 32 * BSTc;
    const int NF = NT / 32;
    const int RP = 2048 / NT;       // B rows per load pass
    const int NPASS = NT / 64;      // load passes (32/RP)
    const int UNIT = (ABUF + BBUFc) * (1 + SPLIT);
    int tid = threadIdx.x, lane = tid & 31, wid = tid >> 5;
    int wm = wid & 1, wn = wid >> 1;
    int g = lane >> 2, tg = lane & 3;
    int m0 = blockIdx.y * 64, n0 = blockIdx.x * NT + n0ofs;
    int Kw = Kd / 2;

    float acc[2 * NF][4];
#pragma unroll
    for (int i = 0; i < 2 * NF; i++)
#pragma unroll
        for (int q = 0; q < 4; q++) acc[i][q] = 0.f;

    int ar = tid >> 2;
    int bkr = tid / (NT / 8), bn8 = (tid % (NT / 8)) * 8;
    const unsigned* ApH = Ah + (size_t)(m0 + ar) * Kw + (tid & 3) * 4;
    const unsigned* ApL = SPLIT ? Al + (size_t)(m0 + ar) * Kw + (tid & 3) * 4 : ApH;
    const __half* BpH = Bh + (size_t)bkr * Nd + n0 + bn8;
    const __half* BpL = SPLIT ? Bl + (size_t)bkr * Nd + n0 + bn8 : BpH;

    int aSts = ar * AST + (tid & 3) * 8;
    int bSts = bkr * BSTc + bn8;

    int aoff[2], boff[NF / 2];
#pragma unroll
    for (int mf = 0; mf < 2; mf++)
        aoff[mf] = (wm * 32 + mf * 16 + (lane & 15)) * AST + (lane >> 4) * 8;
#pragma unroll
    for (int p = 0; p < NF / 2; p++)
        boff[p] = (lane & 15) * BSTc + wn * (NT / 4) + p * 16 + (lane >> 4) * 8;

    uint4 rah, ral, rbh[NPASS], rbl[NPASS];
    rah = *(const uint4*)ApH;
    if (SPLIT) ral = *(const uint4*)ApL;
#pragma unroll
    for (int j = 0; j < NPASS; j++) {
        rbh[j] = *(const uint4*)(BpH + (size_t)(j * RP) * Nd);
        if (SPLIT) rbl[j] = *(const uint4*)(BpL + (size_t)(j * RP) * Nd);
    }
    {
        __half* buf = sh;
        *(uint4*)&buf[aSts] = rah;
        if (SPLIT) *(uint4*)&buf[ABUF + aSts] = ral;
        __half* bb = buf + ABUF * (1 + SPLIT);
#pragma unroll
        for (int j = 0; j < NPASS; j++) {
            *(uint4*)&bb[bSts + j * RP * BSTc] = rbh[j];
            if (SPLIT) *(uint4*)&bb[BBUFc + bSts + j * RP * BSTc] = rbl[j];
        }
    }
    __syncthreads();

    int nit = Kd / 32;
    for (int it = 1; it < nit; it++) {
        rah = *(const uint4*)(ApH + it * 16);
        if (SPLIT) ral = *(const uint4*)(ApL + it * 16);
#pragma unroll
        for (int j = 0; j < NPASS; j++) {
            rbh[j] = *(const uint4*)(BpH + (size_t)(it * 32 + j * RP) * Nd);
            if (SPLIT) rbl[j] = *(const uint4*)(BpL + (size_t)(it * 32 + j * RP) * Nd);
        }
        hg_compute<SPLIT, NT>(sh + ((it - 1) & 1) * UNIT, aoff, boff, acc);
        {
            __half* buf = sh + (it & 1) * UNIT;
            *(uint4*)&buf[aSts] = rah;
            if (SPLIT) *(uint4*)&buf[ABUF + aSts] = ral;
            __half* bb = buf + ABUF * (1 + SPLIT);
#pragma unroll
            for (int j = 0; j < NPASS; j++) {
                *(uint4*)&bb[bSts + j * RP * BSTc] = rbh[j];
                if (SPLIT) *(uint4*)&bb[BBUFc + bSts + j * RP * BSTc] = rbl[j];
            }
        }
        __syncthreads();
    }
    hg_compute<SPLIT, NT>(sh + ((nit - 1) & 1) * UNIT, aoff, boff, acc);

    // epilogue
#pragma unroll
    for (int mf = 0; mf < 2; mf++) {
        int row = m0 + wm * 32 + mf * 16 + g;
#pragma unroll
        for (int nf = 0; nf < NF; nf++) {
            int col = n0 + wn * (NT / 4) + nf * 8 + 2 * tg;
            float b0 = 0.f, b1 = 0.f;
            if (EPI == 0 || EPI == 1) { b0 = bias[col]; b1 = bias[col + 1]; }
#pragma unroll
            for (int half = 0; half < 2; half++) {
                int r = row + half * 8;
                float c0 = acc[mf * NF + nf][half * 2 + 0] + b0;
                float c1 = acc[mf * NF + nf][half * 2 + 1] + b1;
                if (EPI == 0) {
                    size_t base = (size_t)r * ldc + col;
                    float2 rv = *(const float2*)&res[base];
                    float2 ov; ov.x = c0 + rv.x; ov.y = c1 + rv.y;
                    *(float2*)&Cf[base] = ov;
                } else if (EPI == 1) {
                    c0 = 0.5f * c0 * (1.f + erff(c0 * 0.70710678118654752f));
                    c1 = 0.5f * c1 * (1.f + erff(c1 * 0.70710678118654752f));
                    Cu[(size_t)r * (Nd / 2) + col / 2] = packh2(c0, c1);
                } else if (EPI == 2) {
                    int b = r / N_, m = r - b * N_;
                    int part = col >= 768;
                    int rem = col - (part ? 768 : 0);
                    int hd = rem >> 6, d = rem & 63;
                    float s0 = c0, s1 = c1;
                    if (!part) { s0 *= 0.125f; s1 *= 0.125f; }
                    unsigned h, l;
                    splith2(s0, s1, h, l);
                    size_t o = ((size_t)(b * H_ + hd) * NP_ + m) * 32 + (d >> 1);
                    (part ? kh : qh)[o] = h;
                    (part ? kl : ql)[o] = l;
                } else {
                    int b = r / N_, m = r - b * N_;
                    int cv = col - 1536;
                    vh[((size_t)b * NP_ + m) * 384 + (cv >> 1)] = packh2(c0, c1);
                }
            }
        }
    }
}

// ---------------- fused scores + softmax (pre-split Q/K; writes fp16 attn + fp32 diag) ----
__global__ void fsm_kernel(const __half* __restrict__ qhg, const __half* __restrict__ qlg,
                           const __half* __restrict__ khg, const __half* __restrict__ klg,
                           float* __restrict__ diagg, __half* __restrict__ attnh)
{
    __shared__ unsigned Qh[64 * 36], Ql[64 * 36], Kh[32 * 73], Kl[32 * 73];
    __shared__ float red[2][2][64];
    int bh = blockIdx.x;
    int m0 = blockIdx.y * 64;
    int tid = threadIdx.x, lane = tid & 31, wid = tid >> 5;
    int g = lane >> 2, tg = lane & 3;
    int wm = wid & 3, wn = wid >> 2;
    const unsigned* qhw = (const unsigned*)qhg;
    const unsigned* qlw = (const unsigned*)qlg;
    const unsigned* khw = (const unsigned*)khg;
    const unsigned* klw = (const unsigned*)klg;

#pragma unroll
    for (int r = 0; r < 2; r++) {
        int idx = tid + r * 256;
        int row = idx >> 3, w4 = (idx & 7) * 4;
        size_t src = ((size_t)bh * NP_ + m0 + row) * 32 + w4;
        *(uint4*)&Qh[row * 36 + w4] = *(const uint4*)&qhw[src];
        *(uint4*)&Ql[row * 36 + w4] = *(const uint4*)&qlw[src];
    }

    float acc[4][4][4];
#pragma unroll
    for (int c = 0; c < 4; c++)
#pragma unroll
        for (int j = 0; j < 4; j++)
#pragma unroll
            for (int q = 0; q < 4; q++) acc[c][j][q] = 0.f;

    for (int c = 0; c < 4; c++) {
        int n0 = c * 64;
        __syncthreads();
#pragma unroll
        for (int r = 0; r < 2; r++) {
            int idx = tid + r * 256;
            int token = idx >> 3, wp = idx & 7;
            uint4 vh4 = make_uint4(0u, 0u, 0u, 0u), vl4 = make_uint4(0u, 0u, 0u, 0u);
            if (n0 + token < NP_) {
                size_t src = ((size_t)bh * NP_ + n0 + token) * 32 + wp * 4;
                vh4 = *(const uint4*)&khw[src];
                vl4 = *(const uint4*)&klw[src];
            }
            Kh[(wp * 4 + 0) * 73 + token] = vh4.x;
            Kh[(wp * 4 + 1) * 73 + token] = vh4.y;
            Kh[(wp * 4 + 2) * 73 + token] = vh4.z;
            Kh[(wp * 4 + 3) * 73 + token] = vh4.w;
            Kl[(wp * 4 + 0) * 73 + token] = vl4.x;
            Kl[(wp * 4 + 1) * 73 + token] = vl4.y;
            Kl[(wp * 4 + 2) * 73 + token] = vl4.z;
            Kl[(wp * 4 + 3) * 73 + token] = vl4.w;
        }
        __syncthreads();
#pragma unroll
        for (int s = 0; s < 4; s++) {
            int abase = (wm * 16 + g) * 36 + s * 8 + tg;
            unsigned ah[4] = {Qh[abase], Qh[abase + 8 * 36], Qh[abase + 4], Qh[abase + 8 * 36 + 4]};
            unsigned al[4] = {Ql[abase], Ql[abase + 8 * 36], Ql[abase + 4], Ql[abase + 8 * 36 + 4]};
#pragma unroll
            for (int nf = 0; nf < 4; nf++) {
                int n = wn * 32 + nf * 8 + g;
                unsigned bhf[2] = {Kh[(s * 8 + tg) * 73 + n], Kh[(s * 8 + tg + 4) * 73 + n]};
                unsigned blf[2] = {Kl[(s * 8 + tg) * 73 + n], Kl[(s * 8 + tg + 4) * 73 + n]};
                mma_f16(acc[c][nf], ah, bhf);
                mma_f16(acc[c][nf], ah, blf);
                mma_f16(acc[c][nf], al, bhf);
            }
        }
    }

#pragma unroll
    for (int nf = 0; nf < 4; nf++) {
        int col = 192 + wn * 32 + nf * 8 + 2 * tg;
        if (col >= N_)     { acc[3][nf][0] = -1e30f; acc[3][nf][2] = -1e30f; }
        if (col + 1 >= N_) { acc[3][nf][1] = -1e30f; acc[3][nf][3] = -1e30f; }
    }

    int lr0 = wm * 16 + g, lr1 = lr0 + 8;
    float mx0 = -1e30f, mx1 = -1e30f;
#pragma unroll
    for (int c = 0; c < 4; c++)
#pragma unroll
        for (int nf = 0; nf < 4; nf++) {
            mx0 = fmaxf(mx0, fmaxf(acc[c][nf][0], acc[c][nf][1]));
            mx1 = fmaxf(mx1, fmaxf(acc[c][nf][2], acc[c][nf][3]));
        }
    mx0 = fmaxf(mx0, __shfl_xor_sync(0xffffffffu, mx0, 1));
    mx0 = fmaxf(mx0, __shfl_xor_sync(0xffffffffu, mx0, 2));
    mx1 = fmaxf(mx1, __shfl_xor_sync(0xffffffffu, mx1, 1));
    mx1 = fmaxf(mx1, __shfl_xor_sync(0xffffffffu, mx1, 2));
    if (tg == 0) { red[0][wn][lr0] = mx0; red[0][wn][lr1] = mx1; }
    __syncthreads();
    mx0 = fmaxf(red[0][0][lr0], red[0][1][lr0]);
    mx1 = fmaxf(red[0][0][lr1], red[0][1][lr1]);

    float s0 = 0.f, s1 = 0.f;
#pragma unroll
    for (int c = 0; c < 4; c++)
#pragma unroll
        for (int nf = 0; nf < 4; nf++) {
            float e0 = expf(acc[c][nf][0] - mx0);
            float e1 = expf(acc[c][nf][1] - mx0);
            float e2 = expf(acc[c][nf][2] - mx1);
            float e3 = expf(acc[c][nf][3] - mx1);
            acc[c][nf][0] = e0; acc[c][nf][1] = e1;
            acc[c][nf][2] = e2; acc[c][nf][3] = e3;
            s0 += e0 + e1; s1 += e2 + e3;
        }
    s0 += __shfl_xor_sync(0xffffffffu, s0, 1);
    s0 += __shfl_xor_sync(0xffffffffu, s0, 2);
    s1 += __shfl_xor_sync(0xffffffffu, s1, 1);
    s1 += __shfl_xor_sync(0xffffffffu, s1, 2);
    if (tg == 0) { red[1][wn][lr0] = s0; red[1][wn][lr1] = s1; }
    __syncthreads();
    float inv0 = 1.f / (red[1][0][lr0] + red[1][1][lr0]);
    float inv1 = 1.f / (red[1][0][lr1] + red[1][1][lr1]);

    int row0 = m0 + lr0, row1 = m0 + lr1;
    unsigned* hout = (unsigned*)attnh;
#pragma unroll
    for (int c = 0; c < 4; c++)
#pragma unroll
        for (int nf = 0; nf < 4; nf++) {
            int col = c * 64 + wn * 32 + nf * 8 + 2 * tg;
            float v00 = acc[c][nf][0] * inv0, v01 = acc[c][nf][1] * inv0;
            float v10 = acc[c][nf][2] * inv1, v11 = acc[c][nf][3] * inv1;
            if (row0 < N_) {
                if (col == row0)          diagg[(size_t)bh * N_ + row0] = v00;
                else if (col + 1 == row0) diagg[(size_t)bh * N_ + row0] = v01;
            }
            if (row1 < N_) {
                if (col == row1)          diagg[(size_t)bh * N_ + row1] = v10;
                else if (col + 1 == row1) diagg[(size_t)bh * N_ + row1] = v11;
            }
            if (col < NP_) {
                hout[((size_t)bh * 256 + row0) * 112 + col / 2] = packh2(v00, v01);
                hout[((size_t)bh * 256 + row1) * 112 + col / 2] = packh2(v10, v11);
            }
        }
}

// ---------------- AV: all-fp16, ldmatrix both operands ----------------
__global__ void av_mma(const __half* __restrict__ attnh, const __half* __restrict__ vhg,
                       unsigned* __restrict__ aoh)
{
    __shared__ __half As[64 * 40], Vs[32 * 72];
    int bh = blockIdx.x, b = bh / H_, hh = bh % H_;
    int m0 = blockIdx.y * 64;
    int tid = threadIdx.x, lane = tid & 31, wid = tid >> 5;
    int g = lane >> 2, tg = lane & 3;
    int wm = wid & 3, wn = wid >> 2;
    const unsigned* ain = (const unsigned*)attnh;

    float acc[4][4];
#pragma unroll
    for (int i = 0; i < 4; i++)
#pragma unroll
        for (int j = 0; j < 4; j++) acc[i][j] = 0.f;

    int aoff = (wm * 16 + (lane & 15)) * 40 + (lane >> 4) * 8;
    int boff[2];
#pragma unroll
    for (int p = 0; p < 2; p++)
        boff[p] = (lane & 15) * 72 + wn * 32 + p * 16 + (lane >> 4) * 8;

    for (int k0 = 0; k0 < NP_; k0 += 32) {
        __syncthreads();
        {
            int m = tid >> 2, kw4 = (tid & 3) * 4;
            const unsigned* src = ain + ((size_t)bh * 256 + m0 + m) * 112 + k0 / 2 + kw4;
            *(uint4*)&As[m * 40 + (tid & 3) * 8] = *(const uint4*)src;
        }
        {
            int token = tid >> 3, n8 = (tid & 7) * 8;
            const __half* src = vhg + ((size_t)b * NP_ + k0 + token) * C_ + hh * 64 + n8;
            *(uint4*)&Vs[token * 72 + n8] = *(const uint4*)src;
        }
        __syncthreads();
#pragma unroll
        for (int s = 0; s < 2; s++) {
            unsigned ah[4];
            ldsm4(ah, sm_u32(As + aoff + s * 16));
#pragma unroll
            for (int p = 0; p < 2; p++) {
                unsigned r[4];
                ldsm4t(r, sm_u32(Vs + boff[p] + s * 16 * 72));
                unsigned b0[2] = {r[0], r[1]}, b1[2] = {r[2], r[3]};
                mma_f16(acc[2*p],   ah, b0);
                mma_f16(acc[2*p+1], ah, b1);
            }
        }
    }
#pragma unroll
    for (int nf = 0; nf < 4; nf++) {
        int col = wn * 32 + nf * 8 + 2 * tg;
#pragma unroll
        for (int hf = 0; hf < 2; hf++) {
            int m = m0 + wm * 16 + g + hf * 8;
            if (m < N_)
                aoh[(size_t)(b * N_ + m) * 384 + (hh * 64 + col) / 2] =
                    packh2(acc[nf][hf * 2 + 0], acc[nf][hf * 2 + 1]);
        }
    }
}

// ---------------- selection (reads fp32 diag) ----------------
__global__ void select_kernel(const float* __restrict__ diagg, int* __restrict__ ik,
                              int* __restrict__ ie)
{
    __shared__ float diag[196];
    __shared__ int kept[196];
    int b = blockIdx.x, tid = threadIdx.x;
    if (tid < 196) {
        float s = 0.f;
        for (int hh = 0; hh < H_; hh++)
            s += diagg[(size_t)(b * H_ + hh) * N_ + tid + 1];
        diag[tid] = s;
    }
    __syncthreads();
    if (tid < 196) {
        float di = diag[tid];
        int rank = 0;
        for (int j = 0; j < 196; j++) {
            float dj = diag[j];
            rank += (dj > di) || (dj == di && j < tid);
        }
        kept[tid] = (rank < NKEPT_) ? 1 : 0;
    }
    __syncthreads();
    if (tid < 196) {
        int mine = kept[tid];
        int pos = 0;
        for (int j = 0; j < tid; j++) pos += (kept[j] == mine);
        if (mine) ik[b * K_ + 1 + pos] = tid + 1;
        else      ie[b * R_ + pos]     = tid + 1;
    }
    if (tid == 0) ik[b * K_] = 0;
}

// ---------------- propagation (gathers fp16 attn, register bisection) ----------------
#define PT_ 38
__global__ void propagate_kernel(const __half* __restrict__ attnh, const float* __restrict__ x1,
                                 const int* __restrict__ ikg, const int* __restrict__ ieg,
                                 float* __restrict__ x2)
{
    extern __shared__ float sm[];
    float* ws = sm;
    float* xe = sm + K_ * R_;
    __shared__ int ik[K_], ie[R_];
    __shared__ int cnt;
    int bh = blockIdx.x;
    int b = bh / H_, hh = bh % H_;
    int tid = threadIdx.x;
    if (tid < K_) ik[tid] = ikg[b * K_ + tid];
    if (tid < R_) ie[tid] = ieg[b * R_ + tid];
    __syncthreads();
    const __half* ablk = attnh + (size_t)bh * 256 * NP_;
    unsigned uv[PT_];
#pragma unroll
    for (int j = 0; j < PT_; j++) {
        int idx = tid + j * 256;
        float w = 0.f;
        if (idx < K_ * R_) {
            int k = idx / R_, e = idx - k * R_;
            w = __half2float(ablk[(size_t)ik[k] * NP_ + ie[e]]);
            ws[idx] = w;
        }
        uv[j] = __float_as_uint(w);
    }
    for (int idx = tid; idx < R_ * 64; idx += 256) {
        int e = idx >> 6, d = idx & 63;
        xe[idx] = x1[(size_t)(b * N_ + ie[e]) * 768 + hh * 64 + d];
    }
    __syncthreads();

    unsigned lo = 0u, hi = 0x3f801000u;
    while (lo < hi) {
        unsigned mid = lo + ((hi - lo + 1) >> 1);
        if (tid == 0) cnt = 0;
        __syncthreads();
        int local = 0;
#pragma unroll
        for (int j = 0; j < PT_; j++) local += (uv[j] >= mid);
        for (int off = 16; off; off >>= 1) local += __shfl_xor_sync(0xffffffffu, local, off);
        if ((tid & 31) == 0) atomicAdd(&cnt, local);
        __syncthreads();
        int c = cnt;
        __syncthreads();
        if (c >= THRK_) lo = mid; else hi = mid - 1;
    }
    float thr = __uint_as_float(lo);

    for (int p = tid; p < K_ * 64; p += 256) {
        int k = p >> 6, d = p & 63;
        const float* wr = ws + k * R_;
        float acc = 0.f;
#pragma unroll 2
        for (int e = 0; e < R_; e++) {
            float wv = wr[e];
            wv = (wv >= thr) ? wv : 0.f;
            acc = fmaf(wv, xe[e * 64 + d], acc);
        }
        x2[(size_t)(b * K_ + k) * 768 + hh * 64 + d] =
            x1[(size_t)(b * N_ + ik[k]) * 768 + hh * 64 + d] + ALPHA_ * acc;
    }
}

// ---------------- host ----------------
extern "C" void kernel_launch(void* const* d_in, const int* in_sizes, int n_in,
                              void* d_out, int out_size)
{
    const float* x     = (const float*)d_in[0];
    const float* n1g   = (const float*)d_in[1];
    const float* n1b   = (const float*)d_in[2];
    const float* qkvw  = (const float*)d_in[3];
    const float* projw = (const float*)d_in[4];
    const float* projb = (const float*)d_in[5];
    const float* n2g   = (const float*)d_in[6];
    const float* n2b   = (const float*)d_in[7];
    const float* fc1w  = (const float*)d_in[8];
    const float* fc1b  = (const float*)d_in[9];
    const float* fc2w  = (const float*)d_in[10];
    const float* fc2b  = (const float*)d_in[11];
    float* out = (float*)d_out;

    float *diagg, *x1, *x2;
    int *ik, *ie;
    unsigned *hh, *hl, *aoh, *h2h, *mlph;
    __half *wqkvh, *wqkvl, *wprojh, *wfc1h, *wfc2h, *attnh, *qh, *ql, *kh, *kl, *vh;
    cudaGetSymbolAddress((void**)&diagg, g_diag);
    cudaGetSymbolAddress((void**)&attnh, g_attnh);
    cudaGetSymbolAddress((void**)&x1,   g_x1);
    cudaGetSymbolAddress((void**)&x2,   g_x2);
    cudaGetSymbolAddress((void**)&ik,   g_ik);
    cudaGetSymbolAddress((void**)&ie,   g_ie);
    cudaGetSymbolAddress((void**)&hh,   g_hh);
    cudaGetSymbolAddress((void**)&hl,   g_hl);
    cudaGetSymbolAddress((void**)&wqkvh, g_wqkvh);
    cudaGetSymbolAddress((void**)&wqkvl, g_wqkvl);
    cudaGetSymbolAddress((void**)&wprojh, g_wprojh);
    cudaGetSymbolAddress((void**)&wfc1h, g_wfc1h);
    cudaGetSymbolAddress((void**)&wfc2h, g_wfc2h);
    cudaGetSymbolAddress((void**)&qh,   g_qh);
    cudaGetSymbolAddress((void**)&ql,   g_ql);
    cudaGetSymbolAddress((void**)&kh,   g_kh);
    cudaGetSymbolAddress((void**)&kl,   g_kl);
    cudaGetSymbolAddress((void**)&vh,   g_vh);
    cudaGetSymbolAddress((void**)&aoh,  g_aoh);
    cudaGetSymbolAddress((void**)&h2h,  g_h2h);
    cudaGetSymbolAddress((void**)&mlph, g_mlph);

    const int PROP_SMEM = (K_ * R_ + R_ * 64) * 4;
    cudaFuncSetAttribute(propagate_kernel, cudaFuncAttributeMaxDynamicSharedMemorySize, PROP_SMEM);
    const int SMEM_P256 = (ABUF + 32 * 264) * 2 * 2;   // 44032
    const int SMEM_S256 = (ABUF + 32 * 264) * 4 * 2;   // 88064
    const int SMEM_P128 = (ABUF + 32 * 136) * 2 * 2;   // 27648
    cudaFuncSetAttribute(hgemm_kernel<1, 2, 256>, cudaFuncAttributeMaxDynamicSharedMemorySize, SMEM_S256);
    cudaFuncSetAttribute(hgemm_kernel<0, 3, 256>, cudaFuncAttributeMaxDynamicSharedMemorySize, SMEM_P256);
    cudaFuncSetAttribute(hgemm_kernel<0, 0, 256>, cudaFuncAttributeMaxDynamicSharedMemorySize, SMEM_P256);
    cudaFuncSetAttribute(hgemm_kernel<0, 1, 256>, cudaFuncAttributeMaxDynamicSharedMemorySize, SMEM_P256);
    cudaFuncSetAttribute(hgemm_kernel<0, 0, 128>, cudaFuncAttributeMaxDynamicSharedMemorySize, SMEM_P128);

    // 0. weight conversion (single fused launch)
    cvtw_all<<<(S3_ + 255) / 256, 256>>>(qkvw, projw, fc1w, fc2w,
                                         wqkvh, wqkvl, wprojh, wfc1h, wfc2h);
    // 1. LN1 -> packed fp16 hi/lo
    ln_pack_kernel<1><<<B_ * N_, 256>>>(x, n1g, n1b, hh, hl);
    // 2a. QK (split) -> head-major split-fp16 q/k
    hgemm_kernel<1, 2, 256><<<dim3(6, 197), 256, SMEM_S256>>>(
        hh, hl, wqkvh, wqkvl, nullptr, nullptr, nullptr, nullptr,
        (unsigned*)qh, (unsigned*)ql, (unsigned*)kh, (unsigned*)kl, nullptr, 2304, C_, 0, 0);
    // 2b. V (plain) -> head-major fp16 v
    hgemm_kernel<0, 3, 256><<<dim3(3, 197), 256, SMEM_P256>>>(
        hh, nullptr, wqkvh, nullptr, nullptr, nullptr, nullptr, nullptr,
        nullptr, nullptr, nullptr, nullptr, (unsigned*)vh, 2304, C_, 0, 1536);
    // 3. fused scores + softmax -> fp16 attn + fp32 diag
    fsm_kernel<<<dim3(BH_, 4), 256>>>(qh, ql, kh, kl, diagg, attnh);
    // 4. attn @ V
    av_mma<<<dim3(BH_, 4), 256>>>(attnh, vh, aoh);
    // 5. proj + bias + residual
    hgemm_kernel<0, 0, 256><<<dim3(3, 197), 256, SMEM_P256>>>(
        aoh, nullptr, wprojh, nullptr, projb, x, x1, nullptr,
        nullptr, nullptr, nullptr, nullptr, nullptr, C_, C_, C_, 0);
    // 6. selection
    select_kernel<<<B_, 256>>>(diagg, ik, ie);
    // 7. propagation
    propagate_kernel<<<BH_, 256, PROP_SMEM>>>(attnh, x1, ik, ie, x2);
    // 8. LN2 -> packed fp16
    ln_pack_kernel<0><<<B_ * K_, 256>>>(x2, n2g, n2b, h2h, nullptr);
    // 9. fc1 + gelu -> packed fp16
    hgemm_kernel<0, 1, 256><<<dim3(12, 99), 256, SMEM_P256>>>(
        h2h, nullptr, wfc1h, nullptr, fc1b, nullptr, nullptr, mlph,
        nullptr, nullptr, nullptr, nullptr, nullptr, 4 * C_, C_, 0, 0);
    // 10. fc2 + residual -> out (N=128 tiles: 594 blocks -> no 1-block tail wave)
    hgemm_kernel<0, 0, 128><<<dim3(6, 99), 256, SMEM_P128>>>(
        mlph, nullptr, wfc2h, nullptr, fc2b, x2, out, nullptr,
        nullptr, nullptr, nullptr, nullptr, nullptr, C_, 4 * C_, C_, 0);
}